// round 5
// baseline (speedup 1.0000x reference)
#include <cuda_runtime.h>
#include <cuda_bf16.h>
#include <cstdint>
#include <float.h>
#include <math.h>

#define BATCH 4
#define HW    4096
#define CDIM  256
#define NSTRIP 32
#define NPAIR  528
#define EPSQ  1e-9f
#define TLC   0.6f
#define LC    2.0f
#define MARGIN 1.0f
#define SROWB 144                 // padded SMEM row stride (128B data + 16B pad)
#define TENB  (128 * SROWB)       // 128x64 bf16 chunk: 18432 B
#define STAGEB (2 * TENB)         // A-hi + B-hi per chunk: 36864 B
#define TOTSMEM (2 * STAGEB)      // double buffered: 73728 B
#define DPITCH 130                // fp32 D-tile pitch (even -> float2 aligned)

// static device scratch (no allocs anywhere)
__device__ __nv_bfloat16 g_xhi[BATCH * HW * CDIM];
__device__ float  g_norms[BATCH * HW];
__device__ float4 g_pv [BATCH * NSTRIP * 128 * NSTRIP];   // top-4 values
__device__ int4   g_pix[BATCH * NSTRIP * 128 * NSTRIP];   // top-4 indices
__device__ int    g_flagcnt;
__device__ int    g_flaglist[BATCH * HW];

// ---------------------------------------------------------------------------
__device__ __forceinline__ uint32_t smem_u32(const void* p) {
    uint32_t a;
    asm("{ .reg .u64 t; cvta.to.shared.u64 t, %1; cvt.u32.u64 %0, t; }"
        : "=r"(a) : "l"(p));
    return a;
}
__device__ __forceinline__ void cp16(uint32_t dst, const void* src) {
    asm volatile("cp.async.cg.shared.global [%0], [%1], 16;" :: "r"(dst), "l"(src));
}
__device__ __forceinline__ void cp_commit() {
    asm volatile("cp.async.commit_group;" ::: "memory");
}
template <int N> __device__ __forceinline__ void cp_wait() {
    asm volatile("cp.async.wait_group %0;" :: "n"(N) : "memory");
}
__device__ __forceinline__ void ldsm_x4(uint32_t (&r)[4], uint32_t addr) {
    asm volatile("ldmatrix.sync.aligned.m8n8.x4.shared.b16 {%0,%1,%2,%3}, [%4];"
                 : "=r"(r[0]), "=r"(r[1]), "=r"(r[2]), "=r"(r[3]) : "r"(addr));
}
#define MMA16816(d, a, b0_, b1_)                                                 \
    asm volatile("mma.sync.aligned.m16n8k16.row.col.f32.bf16.bf16.f32 "          \
                 "{%0,%1,%2,%3}, {%4,%5,%6,%7}, {%8,%9}, {%0,%1,%2,%3};"         \
                 : "+f"((d)[0]), "+f"((d)[1]), "+f"((d)[2]), "+f"((d)[3])        \
                 : "r"((a)[0]), "r"((a)[1]), "r"((a)[2]), "r"((a)[3]),           \
                   "r"(b0_), "r"(b1_))

// ---- sorted top-4 list with (value, index) lexicographic order -------------
struct L4 { float v0, v1, v2, v3; int i0, i1, i2, i3; };

__device__ __forceinline__ bool ltp(float av, int ai, float bv, int bi) {
    return (av < bv) || (av == bv && ai < bi);
}
__device__ __forceinline__ void ce(float& av, int& ai, float& bv, int& bi) {
    if (!ltp(av, ai, bv, bi)) {
        float t = av; av = bv; bv = t;
        int   u = ai; ai = bi; bi = u;
    }
}
__device__ __forceinline__ void sort4(L4& l) {
    ce(l.v0, l.i0, l.v1, l.i1); ce(l.v2, l.i2, l.v3, l.i3);
    ce(l.v0, l.i0, l.v2, l.i2); ce(l.v1, l.i1, l.v3, l.i3);
    ce(l.v1, l.i1, l.v2, l.i2);
}
__device__ __forceinline__ void mn(float av, int ai, float bv, int bi,
                                   float& rv, int& ri) {
    if (ltp(av, ai, bv, bi)) { rv = av; ri = ai; } else { rv = bv; ri = bi; }
}
// merge two ascending sorted-4, keep smallest 4 ascending (bitonic)
__device__ __forceinline__ L4 merge4(const L4& a, const L4& b) {
    L4 r;
    mn(a.v0, a.i0, b.v3, b.i3, r.v0, r.i0);
    mn(a.v1, a.i1, b.v2, b.i2, r.v1, r.i1);
    mn(a.v2, a.i2, b.v1, b.i1, r.v2, r.i2);
    mn(a.v3, a.i3, b.v0, b.i0, r.v3, r.i3);
    ce(r.v0, r.i0, r.v2, r.i2); ce(r.v1, r.i1, r.v3, r.i3);
    ce(r.v0, r.i0, r.v1, r.i1); ce(r.v2, r.i2, r.v3, r.i3);
    return r;
}
__device__ __forceinline__ L4 shfl_l4(const L4& a, int off) {
    L4 r;
    r.v0 = __shfl_xor_sync(0xffffffffu, a.v0, off);
    r.v1 = __shfl_xor_sync(0xffffffffu, a.v1, off);
    r.v2 = __shfl_xor_sync(0xffffffffu, a.v2, off);
    r.v3 = __shfl_xor_sync(0xffffffffu, a.v3, off);
    r.i0 = __shfl_xor_sync(0xffffffffu, a.i0, off);
    r.i1 = __shfl_xor_sync(0xffffffffu, a.i1, off);
    r.i2 = __shfl_xor_sync(0xffffffffu, a.i2, off);
    r.i3 = __shfl_xor_sync(0xffffffffu, a.i3, off);
    return r;
}
__device__ __forceinline__ float predict(float m1, float m2) {
    float d1 = sqrtf(fmaxf(m1, 0.f) + EPSQ);
    float d2 = sqrtf(fmaxf(m2, 0.f) + EPSQ);
    float e  = expf(d1);
    return (d1 / d2 < TLC) ? 2.f / (1.f + e) : 2.f / (1.f + LC * e);
}

// ---------------------------------------------------------------------------
// Kernel 1: fused bf16-hi convert + fp32 row norms (one warp per row)
// ---------------------------------------------------------------------------
__global__ void convert_norms_kernel(const float* __restrict__ x) {
    if (blockIdx.x == 0 && threadIdx.x == 0) g_flagcnt = 0;
    int gw   = (blockIdx.x * blockDim.x + threadIdx.x) >> 5;
    int lane = threadIdx.x & 31;
    if (gw >= BATCH * HW) return;
    const float* xr = x + (size_t)gw * CDIM + lane * 8;
    float4 v0 = *(const float4*)xr;
    float4 v1 = *(const float4*)(xr + 4);
    float s = v0.x*v0.x + v0.y*v0.y + v0.z*v0.z + v0.w*v0.w
            + v1.x*v1.x + v1.y*v1.y + v1.z*v1.z + v1.w*v1.w;
    __nv_bfloat162 p0(__float2bfloat16(v0.x), __float2bfloat16(v0.y));
    __nv_bfloat162 p1(__float2bfloat16(v0.z), __float2bfloat16(v0.w));
    __nv_bfloat162 p2(__float2bfloat16(v1.x), __float2bfloat16(v1.y));
    __nv_bfloat162 p3(__float2bfloat16(v1.z), __float2bfloat16(v1.w));
    uint4 u;
    u.x = *(uint32_t*)&p0; u.y = *(uint32_t*)&p1;
    u.z = *(uint32_t*)&p2; u.w = *(uint32_t*)&p3;
    ((uint4*)g_xhi)[(size_t)gw * 32 + lane] = u;
    #pragma unroll
    for (int o = 16; o; o >>= 1) s += __shfl_xor_sync(0xffffffffu, s, o);
    if (lane == 0) g_norms[gw] = s;
}

// ---------------------------------------------------------------------------
// Kernel 2: bf16 single-pass Gram tile-pair + per-row/col top-4 partials.
// CTA = upper-tri pair (i,j); 1024 threads; warp tile m16n32.
// ---------------------------------------------------------------------------
__global__ __launch_bounds__(1024, 1)
void fcm_pair_kernel() {
    extern __shared__ __align__(16) char smem[];
    const uint32_t sbase = smem_u32(smem);

    const int tid  = threadIdx.x;
    const int lane = tid & 31;
    const int w    = tid >> 5;          // 0..31
    const int mw   = w >> 2;            // 0..7 (16-row group)
    const int nw   = w & 3;             // 0..3 (32-col group)
    const int b    = blockIdx.y;

    int p = blockIdx.x;
    int i = (int)((65.0f - sqrtf(4225.0f - 8.0f * (float)p)) * 0.5f);
    while ((i + 1) * (65 - (i + 1)) / 2 <= p) ++i;
    while (i * (65 - i) / 2 > p) --i;
    const int j = i + (p - i * (65 - i) / 2);
    const int row0 = i * 128, col0 = j * 128;
    const bool diag = (i == j);

    const __nv_bfloat16* xb = g_xhi + (size_t)b * HW * CDIM;
    const int lrow = lane & 15;
    const int lkb  = (lane >> 4) * 16;

    auto stage = [&](int kc) {
        const uint32_t dst = sbase + (uint32_t)((kc & 1) * STAGEB);
        int r = tid >> 3, gg = tid & 7;
        cp16(dst + (uint32_t)(r * SROWB + gg * 16),
             xb + (size_t)(row0 + r) * CDIM + kc * 64 + gg * 8);
        cp16(dst + TENB + (uint32_t)(r * SROWB + gg * 16),
             xb + (size_t)(col0 + r) * CDIM + kc * 64 + gg * 8);
        cp_commit();
    };
    stage(0);

    float acc[4][4];
    #pragma unroll
    for (int nf = 0; nf < 4; ++nf)
        #pragma unroll
        for (int e = 0; e < 4; ++e) acc[nf][e] = 0.f;

    for (int kc = 0; kc < 4; ++kc) {
        cp_wait<0>();
        __syncthreads();
        if (kc < 3) stage(kc + 1);
        const uint32_t bb  = sbase + (uint32_t)((kc & 1) * STAGEB);
        const uint32_t ab  = bb + (uint32_t)((mw * 16 + lrow) * SROWB);
        const uint32_t bbs = bb + TENB + (uint32_t)((nw * 32 + lrow) * SROWB);
        #pragma unroll
        for (int ks = 0; ks < 4; ++ks) {
            const uint32_t kb = (uint32_t)(ks * 32 + lkb);
            uint32_t ah[4], bh[2][4];
            ldsm_x4(ah, ab + kb);
            ldsm_x4(bh[0], bbs + kb);
            ldsm_x4(bh[1], bbs + 16 * SROWB + kb);
            #pragma unroll
            for (int nf = 0; nf < 4; ++nf)
                MMA16816(acc[nf], ah, bh[nf >> 1][nf & 1], bh[nf >> 1][(nf & 1) + 2]);
        }
    }
    __syncthreads();                       // all ldsm done; alias smem as D tile

    // ---- D tile (fp32 squared distances) into SMEM ----
    float* Dt = (float*)smem;
    const int r0l = mw * 16 + (lane >> 2);
    const float na0 = g_norms[b * HW + row0 + r0l];
    const float na1 = g_norms[b * HW + row0 + r0l + 8];
    const float* nbp = g_norms + b * HW + col0 + nw * 32 + (lane & 3) * 2;
    #pragma unroll
    for (int nf = 0; nf < 4; ++nf) {
        float2 nb = *(const float2*)(nbp + nf * 8);
        int cl = nw * 32 + nf * 8 + (lane & 3) * 2;
        float2 d0 = { na0 + nb.x - 2.f * acc[nf][0], na0 + nb.y - 2.f * acc[nf][1] };
        float2 d1 = { na1 + nb.x - 2.f * acc[nf][2], na1 + nb.y - 2.f * acc[nf][3] };
        *(float2*)&Dt[r0l * DPITCH + cl]       = d0;
        *(float2*)&Dt[(r0l + 8) * DPITCH + cl] = d1;
    }
    __syncthreads();

    // ---- row-side top-4 (warp w -> rows 4w..4w+3) ----
    #pragma unroll
    for (int q = 0; q < 4; ++q) {
        const int rr = w * 4 + q;
        float a0 = Dt[rr * DPITCH + lane];
        float a1 = Dt[rr * DPITCH + lane + 32];
        float a2 = Dt[rr * DPITCH + lane + 64];
        float a3 = Dt[rr * DPITCH + lane + 96];
        if (diag) {
            if (lane      == rr) a0 = FLT_MAX;
            if (lane + 32 == rr) a1 = FLT_MAX;
            if (lane + 64 == rr) a2 = FLT_MAX;
            if (lane + 96 == rr) a3 = FLT_MAX;
        }
        L4 l = { a0, a1, a2, a3,
                 col0 + lane, col0 + lane + 32, col0 + lane + 64, col0 + lane + 96 };
        sort4(l);
        #pragma unroll
        for (int off = 1; off <= 16; off <<= 1) l = merge4(l, shfl_l4(l, off));
        if (lane == 0) {
            size_t o = ((size_t)(b * NSTRIP + i) * 128 + rr) * NSTRIP + j;
            g_pv[o]  = make_float4(l.v0, l.v1, l.v2, l.v3);
            g_pix[o] = make_int4(l.i0, l.i1, l.i2, l.i3);
        }
    }

    // ---- col-side top-4 (warp w -> cols 4w..4w+3), skip on diagonal ----
    if (!diag) {
        #pragma unroll
        for (int q = 0; q < 4; ++q) {
            const int cc = w * 4 + q;
            float a0 = Dt[(lane)      * DPITCH + cc];
            float a1 = Dt[(lane + 32) * DPITCH + cc];
            float a2 = Dt[(lane + 64) * DPITCH + cc];
            float a3 = Dt[(lane + 96) * DPITCH + cc];
            L4 l = { a0, a1, a2, a3,
                     row0 + lane, row0 + lane + 32, row0 + lane + 64, row0 + lane + 96 };
            sort4(l);
            #pragma unroll
            for (int off = 1; off <= 16; off <<= 1) l = merge4(l, shfl_l4(l, off));
            if (lane == 0) {
                size_t o = ((size_t)(b * NSTRIP + j) * 128 + cc) * NSTRIP + i;
                g_pv[o]  = make_float4(l.v0, l.v1, l.v2, l.v3);
                g_pix[o] = make_int4(l.i0, l.i1, l.i2, l.i3);
            }
        }
    }
}

// ---------------------------------------------------------------------------
// Kernel 3: merge 32 slot-partials per row, refine top-4 exactly in fp32,
// emit outputs; flag rows whose guarantee margin fails.
// ---------------------------------------------------------------------------
__global__ void merge_refine_kernel(const float* __restrict__ x,
                                    float* __restrict__ out, int out_size) {
    int gw   = (blockIdx.x * blockDim.x + threadIdx.x) >> 5;
    int lane = threadIdx.x & 31;
    if (gw >= BATCH * HW) return;
    const int b = gw >> 12, rl = gw & 4095;
    const int strip = rl >> 7, rr = rl & 127;

    size_t pidx = ((size_t)(b * NSTRIP + strip) * 128 + rr) * NSTRIP + lane;
    float4 pv = g_pv[pidx];
    int4   pi = g_pix[pidx];
    L4 l = { pv.x, pv.y, pv.z, pv.w, pi.x, pi.y, pi.z, pi.w };
    #pragma unroll
    for (int off = 1; off <= 16; off <<= 1) l = merge4(l, shfl_l4(l, off));

    // exact fp32 refinement of the 4 candidates
    const float* xb = x + (size_t)b * HW * CDIM;
    const float* xr = xb + (size_t)rl * CDIM + lane * 8;
    float4 a0 = *(const float4*)xr;
    float4 a1 = *(const float4*)(xr + 4);
    const float nr = g_norms[b * HW + rl];

    auto exact = [&](int c) -> float {
        const float* xc = xb + (size_t)c * CDIM + lane * 8;
        float4 c0 = *(const float4*)xc;
        float4 c1 = *(const float4*)(xc + 4);
        float s = a0.x*c0.x + a0.y*c0.y + a0.z*c0.z + a0.w*c0.w
                + a1.x*c1.x + a1.y*c1.y + a1.z*c1.z + a1.w*c1.w;
        #pragma unroll
        for (int o = 16; o; o >>= 1) s += __shfl_xor_sync(0xffffffffu, s, o);
        return nr + g_norms[b * HW + c] - 2.f * s;
    };
    L4 E = { exact(l.i0), exact(l.i1), exact(l.i2), exact(l.i3),
             l.i0, l.i1, l.i2, l.i3 };
    sort4(E);

    if (lane == 0) {
        out[(size_t)b * HW + rl] = predict(E.v0, E.v1);
        if (out_size >= 2 * BATCH * HW)
            out[(size_t)BATCH * HW + (size_t)b * HW + rl] = (float)E.i0;
        // guarantee: non-candidates have D_exact >= l.v3 - MARGIN
        if (E.v1 > l.v3 - MARGIN) {
            int fi = atomicAdd(&g_flagcnt, 1);
            g_flaglist[fi] = gw;
        }
    }
}

// ---------------------------------------------------------------------------
// Kernel 4: exact full-row rescan for flagged rows (expected: a handful).
// ---------------------------------------------------------------------------
__global__ void fallback_kernel(const float* __restrict__ x,
                                float* __restrict__ out, int out_size) {
    __shared__ float sv1[256], sv2[256];
    __shared__ int   si1[256];
    const int n = g_flagcnt;
    for (int fi = blockIdx.x; fi < n; fi += gridDim.x) {
        const int rowg = g_flaglist[fi];
        const int b = rowg >> 12, r = rowg & 4095;
        const float* xb = x + (size_t)b * HW * CDIM;
        const float* xr = xb + (size_t)r * CDIM;
        const float  nr = g_norms[rowg];
        float v1 = FLT_MAX, v2 = FLT_MAX; int i1 = 0;
        for (int c = threadIdx.x; c < HW; c += 256) {
            if (c == r) continue;
            const float4* xc = (const float4*)(xb + (size_t)c * CDIM);
            float s = 0.f;
            #pragma unroll
            for (int d = 0; d < 64; ++d) {
                float4 va = ((const float4*)xr)[d];
                float4 vb = xc[d];
                s += va.x*vb.x + va.y*vb.y + va.z*vb.z + va.w*vb.w;
            }
            float D = nr + g_norms[b * HW + c] - 2.f * s;
            if (D < v1) { v2 = v1; v1 = D; i1 = c; }
            else if (D < v2) { v2 = D; }
        }
        sv1[threadIdx.x] = v1; sv2[threadIdx.x] = v2; si1[threadIdx.x] = i1;
        __syncthreads();
        for (int off = 128; off; off >>= 1) {
            if (threadIdx.x < off) {
                float b1 = sv1[threadIdx.x + off], b2 = sv2[threadIdx.x + off];
                int   bi = si1[threadIdx.x + off];
                float a1v = sv1[threadIdx.x]; int a1i = si1[threadIdx.x];
                if (ltp(b1, bi, a1v, a1i)) {
                    sv2[threadIdx.x] = fminf(a1v, b2);
                    sv1[threadIdx.x] = b1; si1[threadIdx.x] = bi;
                } else {
                    sv2[threadIdx.x] = fminf(sv2[threadIdx.x], b1);
                }
            }
            __syncthreads();
        }
        if (threadIdx.x == 0) {
            out[(size_t)b * HW + r] = predict(sv1[0], sv2[0]);
            if (out_size >= 2 * BATCH * HW)
                out[(size_t)BATCH * HW + (size_t)b * HW + r] = (float)si1[0];
        }
        __syncthreads();
    }
}

// ---------------------------------------------------------------------------
extern "C" void kernel_launch(void* const* d_in, const int* in_sizes, int n_in,
                              void* d_out, int out_size) {
    const float* x   = (const float*)d_in[0];
    float*       out = (float*)d_out;

    convert_norms_kernel<<<BATCH * HW / 8, 256>>>(x);

    cudaFuncSetAttribute(fcm_pair_kernel,
                         cudaFuncAttributeMaxDynamicSharedMemorySize, TOTSMEM);
    dim3 grid(NPAIR, BATCH);
    fcm_pair_kernel<<<grid, 1024, TOTSMEM>>>();

    merge_refine_kernel<<<BATCH * HW / 8, 256>>>(x, out, out_size);
    fallback_kernel<<<256, 256>>>(x, out, out_size);
}

// round 6
// speedup vs baseline: 2.6960x; 2.6960x over previous
#include <cuda_runtime.h>
#include <cuda_bf16.h>
#include <cstdint>
#include <float.h>
#include <math.h>

#define BATCH 4
#define HW    4096
#define CDIM  256
#define NSTRIP 32
#define NPAIR  528
#define EPSQ  1e-9f
#define TLC   0.6f
#define LC    2.0f
#define MARGIN 0.75f
#define SROWB 144                 // padded SMEM row stride (128B data + 16B pad)
#define TENB  (128 * SROWB)       // 128x64 bf16 chunk: 18432 B
#define STAGEB (2 * TENB)         // A-hi + B-hi per chunk: 36864 B
#define TOTSMEM (2 * STAGEB)      // double buffered: 73728 B
#define DPITCH 130                // fp32 D-tile pitch

// static device scratch
__device__ __nv_bfloat16 g_xhi[BATCH * HW * CDIM];
__device__ float  g_norms[BATCH * HW];
__device__ float4 g_pv [2u * BATCH * HW * NSTRIP];   // top-8 values (2 float4/slot)
__device__ int4   g_pix[2u * BATCH * HW * NSTRIP];   // top-8 indices
__device__ int    g_flagcnt;
__device__ int    g_flaglist[BATCH * HW];

// ---------------------------------------------------------------------------
__device__ __forceinline__ uint32_t smem_u32(const void* p) {
    uint32_t a;
    asm("{ .reg .u64 t; cvta.to.shared.u64 t, %1; cvt.u32.u64 %0, t; }"
        : "=r"(a) : "l"(p));
    return a;
}
__device__ __forceinline__ void cp16(uint32_t dst, const void* src) {
    asm volatile("cp.async.cg.shared.global [%0], [%1], 16;" :: "r"(dst), "l"(src));
}
__device__ __forceinline__ void cp_commit() {
    asm volatile("cp.async.commit_group;" ::: "memory");
}
template <int N> __device__ __forceinline__ void cp_wait() {
    asm volatile("cp.async.wait_group %0;" :: "n"(N) : "memory");
}
__device__ __forceinline__ void ldsm_x4(uint32_t (&r)[4], uint32_t addr) {
    asm volatile("ldmatrix.sync.aligned.m8n8.x4.shared.b16 {%0,%1,%2,%3}, [%4];"
                 : "=r"(r[0]), "=r"(r[1]), "=r"(r[2]), "=r"(r[3]) : "r"(addr));
}
#define MMA16816(d, a, b0_, b1_)                                                 \
    asm volatile("mma.sync.aligned.m16n8k16.row.col.f32.bf16.bf16.f32 "          \
                 "{%0,%1,%2,%3}, {%4,%5,%6,%7}, {%8,%9}, {%0,%1,%2,%3};"         \
                 : "+f"((d)[0]), "+f"((d)[1]), "+f"((d)[2]), "+f"((d)[3])        \
                 : "r"((a)[0]), "r"((a)[1]), "r"((a)[2]), "r"((a)[3]),           \
                   "r"(b0_), "r"(b1_))

// ---- (value,index) lexicographic helpers + sorted-8 lists -------------------
__device__ __forceinline__ bool ltp(float av, int ai, float bv, int bi) {
    return (av < bv) || (av == bv && ai < bi);
}
__device__ __forceinline__ void mn(float av, int ai, float bv, int bi,
                                   float& rv, int& ri) {
    if (ltp(av, ai, bv, bi)) { rv = av; ri = ai; } else { rv = bv; ri = bi; }
}
struct L8 { float v[8]; int ix[8]; };
__device__ __forceinline__ void ce8(L8& l, int a, int b) {
    if (!ltp(l.v[a], l.ix[a], l.v[b], l.ix[b])) {
        float t = l.v[a]; l.v[a] = l.v[b]; l.v[b] = t;
        int   u = l.ix[a]; l.ix[a] = l.ix[b]; l.ix[b] = u;
    }
}
__device__ __forceinline__ void bsort8(L8& l) {   // bitonic sequence -> ascending
    ce8(l,0,4); ce8(l,1,5); ce8(l,2,6); ce8(l,3,7);
    ce8(l,0,2); ce8(l,1,3); ce8(l,4,6); ce8(l,5,7);
    ce8(l,0,1); ce8(l,2,3); ce8(l,4,5); ce8(l,6,7);
}
__device__ __forceinline__ L8 merge8(const L8& a, const L8& b) {   // both asc
    L8 r;
    #pragma unroll
    for (int k = 0; k < 8; ++k)
        mn(a.v[k], a.ix[k], b.v[7 - k], b.ix[7 - k], r.v[k], r.ix[k]);
    bsort8(r);
    return r;
}
__device__ __forceinline__ L8 shfl8(const L8& a, int off) {
    L8 r;
    #pragma unroll
    for (int k = 0; k < 8; ++k) {
        r.v[k]  = __shfl_xor_sync(0xffffffffu, a.v[k],  off);
        r.ix[k] = __shfl_xor_sync(0xffffffffu, a.ix[k], off);
    }
    return r;
}
__device__ __forceinline__ void ins8(L8& l, float d, int c) {
    if (ltp(d, c, l.v[7], l.ix[7])) {
        l.v[7] = d; l.ix[7] = c;
        #pragma unroll
        for (int k = 7; k > 0; --k) ce8(l, k - 1, k);
    }
}
__device__ __forceinline__ float predict(float m1, float m2) {
    float d1 = sqrtf(fmaxf(m1, 0.f) + EPSQ);
    float d2 = sqrtf(fmaxf(m2, 0.f) + EPSQ);
    float e  = expf(d1);
    return (d1 / d2 < TLC) ? 2.f / (1.f + e) : 2.f / (1.f + LC * e);
}

// ---------------------------------------------------------------------------
// Kernel 1: fused bf16 convert + fp32 row norms (one warp per row)
// ---------------------------------------------------------------------------
__global__ void convert_norms_kernel(const float* __restrict__ x) {
    if (blockIdx.x == 0 && threadIdx.x == 0) g_flagcnt = 0;
    int gw   = (blockIdx.x * blockDim.x + threadIdx.x) >> 5;
    int lane = threadIdx.x & 31;
    if (gw >= BATCH * HW) return;
    const float* xr = x + (size_t)gw * CDIM + lane * 8;
    float4 v0 = *(const float4*)xr;
    float4 v1 = *(const float4*)(xr + 4);
    float s = v0.x*v0.x + v0.y*v0.y + v0.z*v0.z + v0.w*v0.w
            + v1.x*v1.x + v1.y*v1.y + v1.z*v1.z + v1.w*v1.w;
    __nv_bfloat162 p0(__float2bfloat16(v0.x), __float2bfloat16(v0.y));
    __nv_bfloat162 p1(__float2bfloat16(v0.z), __float2bfloat16(v0.w));
    __nv_bfloat162 p2(__float2bfloat16(v1.x), __float2bfloat16(v1.y));
    __nv_bfloat162 p3(__float2bfloat16(v1.z), __float2bfloat16(v1.w));
    uint4 u;
    u.x = *(uint32_t*)&p0; u.y = *(uint32_t*)&p1;
    u.z = *(uint32_t*)&p2; u.w = *(uint32_t*)&p3;
    ((uint4*)g_xhi)[(size_t)gw * 32 + lane] = u;
    #pragma unroll
    for (int o = 16; o; o >>= 1) s += __shfl_xor_sync(0xffffffffu, s, o);
    if (lane == 0) g_norms[gw] = s;
}

// ---------------------------------------------------------------------------
// Kernel 2: single-pass bf16 Gram tile-pair (512 thr, R4 mainloop) +
// per-row / per-col top-8 partials into global scratch.
// ---------------------------------------------------------------------------
__global__ __launch_bounds__(512, 1)
void fcm_pair_kernel() {
    extern __shared__ __align__(16) char smem[];
    const uint32_t sbase = smem_u32(smem);

    const int tid  = threadIdx.x;
    const int lane = tid & 31;
    const int w    = tid >> 5;
    const int mw   = w >> 2;
    const int nw   = w & 3;
    const int b    = blockIdx.y;

    int p = blockIdx.x;
    int i = (int)((65.0f - sqrtf(4225.0f - 8.0f * (float)p)) * 0.5f);
    while ((i + 1) * (65 - (i + 1)) / 2 <= p) ++i;
    while (i * (65 - i) / 2 > p) --i;
    const int j = i + (p - i * (65 - i) / 2);
    const int row0 = i * 128, col0 = j * 128;
    const bool diag = (i == j);

    const __nv_bfloat16* xb = g_xhi + (size_t)b * HW * CDIM;
    const int lrow = ((lane >> 3) & 1) * 8 + (lane & 7);
    const int lkb  = (lane >> 4) * 16;

    auto stage = [&](int kc) {
        const uint32_t dst = sbase + (uint32_t)((kc & 1) * STAGEB);
        #pragma unroll
        for (int o = 0; o < 2; ++o) {
            int lin = tid + o * 512;
            int r = lin >> 3, gg = lin & 7;
            cp16(dst + (uint32_t)(r * SROWB + gg * 16),
                 xb + (size_t)(row0 + r) * CDIM + kc * 64 + gg * 8);
            cp16(dst + TENB + (uint32_t)(r * SROWB + gg * 16),
                 xb + (size_t)(col0 + r) * CDIM + kc * 64 + gg * 8);
        }
        cp_commit();
    };
    stage(0);

    float acc[2][4][4];
    #pragma unroll
    for (int mf = 0; mf < 2; ++mf)
        #pragma unroll
        for (int nf = 0; nf < 4; ++nf)
            #pragma unroll
            for (int e = 0; e < 4; ++e) acc[mf][nf][e] = 0.f;

    for (int kc = 0; kc < 4; ++kc) {
        cp_wait<0>();
        __syncthreads();
        if (kc < 3) stage(kc + 1);
        const uint32_t bb   = sbase + (uint32_t)((kc & 1) * STAGEB);
        const uint32_t ab   = bb + (uint32_t)((mw * 32 + lrow) * SROWB);
        const uint32_t bbs  = bb + TENB + (uint32_t)((nw * 32 + lrow) * SROWB);
        #pragma unroll
        for (int ks = 0; ks < 4; ++ks) {
            const uint32_t kb = (uint32_t)(ks * 32 + lkb);
            uint32_t ah[2][4], bh[2][4];
            ldsm_x4(ah[0], ab + kb);
            ldsm_x4(ah[1], ab + 16 * SROWB + kb);
            ldsm_x4(bh[0], bbs + kb);
            ldsm_x4(bh[1], bbs + 16 * SROWB + kb);
            #pragma unroll
            for (int mf = 0; mf < 2; ++mf)
                #pragma unroll
                for (int nf = 0; nf < 4; ++nf)
                    MMA16816(acc[mf][nf], ah[mf],
                             bh[nf >> 1][nf & 1], bh[nf >> 1][(nf & 1) + 2]);
        }
    }
    __syncthreads();                 // ldsm done; alias smem as fp32 D-tile

    // ---- D tile into SMEM ----
    float* Dt = (float*)smem;
    #pragma unroll
    for (int mf = 0; mf < 2; ++mf) {
        const int r0l = mw * 32 + mf * 16 + (lane >> 2);
        const float na0 = g_norms[b * HW + row0 + r0l];
        const float na1 = g_norms[b * HW + row0 + r0l + 8];
        const float* nbp = g_norms + b * HW + col0 + nw * 32 + (lane & 3) * 2;
        #pragma unroll
        for (int nf = 0; nf < 4; ++nf) {
            float2 nb = *(const float2*)(nbp + nf * 8);
            int cl = nw * 32 + nf * 8 + (lane & 3) * 2;
            float2 d0 = { na0 + nb.x - 2.f * acc[mf][nf][0],
                          na0 + nb.y - 2.f * acc[mf][nf][1] };
            float2 d1 = { na1 + nb.x - 2.f * acc[mf][nf][2],
                          na1 + nb.y - 2.f * acc[mf][nf][3] };
            *(float2*)&Dt[r0l * DPITCH + cl]       = d0;
            *(float2*)&Dt[(r0l + 8) * DPITCH + cl] = d1;
        }
    }
    __syncthreads();

    const int rr  = tid >> 2;        // 0..127
    const int sub = tid & 3;

    // ---- row-side top-8 (4 threads per row, bank-staggered scan) ----
    {
        L8 l;
        #pragma unroll
        for (int k = 0; k < 8; ++k) { l.v[k] = FLT_MAX; l.ix[k] = 0x7fffffff; }
        for (int it = 0; it < 32; ++it) {
            int c  = sub * 32 + ((it + 8 * sub) & 31);
            int gc = col0 + c;
            if (diag && gc == row0 + rr) continue;
            ins8(l, Dt[rr * DPITCH + c], gc);
        }
        l = merge8(l, shfl8(l, 1));
        l = merge8(l, shfl8(l, 2));
        if (sub == 0) {
            size_t o = 2 * (((size_t)(b * NSTRIP + i) * 128 + rr) * NSTRIP + j);
            g_pv[o]      = make_float4(l.v[0], l.v[1], l.v[2], l.v[3]);
            g_pv[o + 1]  = make_float4(l.v[4], l.v[5], l.v[6], l.v[7]);
            g_pix[o]     = make_int4(l.ix[0], l.ix[1], l.ix[2], l.ix[3]);
            g_pix[o + 1] = make_int4(l.ix[4], l.ix[5], l.ix[6], l.ix[7]);
        }
    }

    // ---- col-side top-8 (skipped for diagonal pairs) ----
    if (!diag) {
        L8 l;
        #pragma unroll
        for (int k = 0; k < 8; ++k) { l.v[k] = FLT_MAX; l.ix[k] = 0x7fffffff; }
        for (int it = 0; it < 32; ++it) {
            int r = sub * 32 + ((it + 8 * sub) & 31);
            ins8(l, Dt[r * DPITCH + rr], row0 + r);
        }
        l = merge8(l, shfl8(l, 1));
        l = merge8(l, shfl8(l, 2));
        if (sub == 0) {
            size_t o = 2 * (((size_t)(b * NSTRIP + j) * 128 + rr) * NSTRIP + i);
            g_pv[o]      = make_float4(l.v[0], l.v[1], l.v[2], l.v[3]);
            g_pv[o + 1]  = make_float4(l.v[4], l.v[5], l.v[6], l.v[7]);
            g_pix[o]     = make_int4(l.ix[0], l.ix[1], l.ix[2], l.ix[3]);
            g_pix[o + 1] = make_int4(l.ix[4], l.ix[5], l.ix[6], l.ix[7]);
        }
    }
}

// ---------------------------------------------------------------------------
// Kernel 3: merge 32 slot top-8s per row, exact fp32 refine of the global
// top-8, emit outputs; flag rows whose guarantee margin fails.
// ---------------------------------------------------------------------------
__global__ void merge_refine_kernel(const float* __restrict__ x,
                                    float* __restrict__ out, int out_size) {
    int gw   = (blockIdx.x * blockDim.x + threadIdx.x) >> 5;
    int lane = threadIdx.x & 31;
    if (gw >= BATCH * HW) return;
    const int b = gw >> 12, rl = gw & 4095;

    size_t o = 2 * ((size_t)gw * NSTRIP + lane);
    float4 v0 = g_pv[o], v1 = g_pv[o + 1];
    int4   x0 = g_pix[o], x1 = g_pix[o + 1];
    L8 l = { { v0.x, v0.y, v0.z, v0.w, v1.x, v1.y, v1.z, v1.w },
             { x0.x, x0.y, x0.z, x0.w, x1.x, x1.y, x1.z, x1.w } };
    #pragma unroll
    for (int off = 1; off <= 16; off <<= 1) l = merge8(l, shfl8(l, off));

    // exact fp32 refinement of the 8 global candidates
    const float* xb = x + (size_t)b * HW * CDIM;
    const float* xr = xb + (size_t)rl * CDIM + lane * 8;
    float4 a0 = *(const float4*)xr;
    float4 a1 = *(const float4*)(xr + 4);
    const float nr = g_norms[b * HW + rl];

    float m1 = FLT_MAX, m2 = FLT_MAX; int j1 = 0, j2 = 0;
    #pragma unroll
    for (int k = 0; k < 8; ++k) {
        const int c = l.ix[k];
        const float* xc = xb + (size_t)c * CDIM + lane * 8;
        float4 c0 = *(const float4*)xc;
        float4 c1 = *(const float4*)(xc + 4);
        float s = a0.x*c0.x + a0.y*c0.y + a0.z*c0.z + a0.w*c0.w
                + a1.x*c1.x + a1.y*c1.y + a1.z*c1.z + a1.w*c1.w;
        #pragma unroll
        for (int off = 16; off; off >>= 1) s += __shfl_xor_sync(0xffffffffu, s, off);
        float D = nr + g_norms[b * HW + c] - 2.f * s;
        if (ltp(D, c, m1, j1)) { m2 = m1; j2 = j1; m1 = D; j1 = c; }
        else if (ltp(D, c, m2, j2)) { m2 = D; j2 = c; }
    }

    if (lane == 0) {
        out[(size_t)b * HW + rl] = predict(m1, m2);
        if (out_size >= 2 * BATCH * HW)
            out[(size_t)BATCH * HW + (size_t)b * HW + rl] = (float)j1;
        // guarantee: non-candidates have D_bf16 >= l.v[7] => D_exact >= l.v[7]-MARGIN
        if (m2 > l.v[7] - MARGIN) {
            int fi = atomicAdd(&g_flagcnt, 1);
            g_flaglist[fi] = gw;
        }
    }
}

// ---------------------------------------------------------------------------
// Kernel 4: exact full-row rescan for flagged rows (expected ~0 rows).
// ---------------------------------------------------------------------------
__global__ void fallback_kernel(const float* __restrict__ x,
                                float* __restrict__ out, int out_size) {
    __shared__ float sv1[256], sv2[256];
    __shared__ int   si1[256];
    const int n = g_flagcnt;
    for (int fi = blockIdx.x; fi < n; fi += gridDim.x) {
        const int rowg = g_flaglist[fi];
        const int b = rowg >> 12, r = rowg & 4095;
        const float* xb = x + (size_t)b * HW * CDIM;
        const float* xr = xb + (size_t)r * CDIM;
        const float  nr = g_norms[rowg];
        float v1 = FLT_MAX, v2 = FLT_MAX; int i1 = 0x7fffffff;
        for (int c = threadIdx.x; c < HW; c += 256) {
            if (c == r) continue;
            const float4* xc = (const float4*)(xb + (size_t)c * CDIM);
            float s = 0.f;
            #pragma unroll
            for (int d = 0; d < 64; ++d) {
                float4 va = ((const float4*)xr)[d];
                float4 vb = xc[d];
                s += va.x*vb.x + va.y*vb.y + va.z*vb.z + va.w*vb.w;
            }
            float D = nr + g_norms[b * HW + c] - 2.f * s;
            if (ltp(D, c, v1, i1)) { v2 = v1; v1 = D; i1 = c; }
            else if (D < v2) { v2 = D; }
        }
        sv1[threadIdx.x] = v1; sv2[threadIdx.x] = v2; si1[threadIdx.x] = i1;
        __syncthreads();
        for (int off = 128; off; off >>= 1) {
            if (threadIdx.x < off) {
                float b1 = sv1[threadIdx.x + off], b2 = sv2[threadIdx.x + off];
                int   bi = si1[threadIdx.x + off];
                float a1v = sv1[threadIdx.x]; int a1i = si1[threadIdx.x];
                if (ltp(b1, bi, a1v, a1i)) {
                    sv2[threadIdx.x] = fminf(a1v, b2);
                    sv1[threadIdx.x] = b1; si1[threadIdx.x] = bi;
                } else {
                    sv2[threadIdx.x] = fminf(sv2[threadIdx.x], b1);
                }
            }
            __syncthreads();
        }
        if (threadIdx.x == 0) {
            out[(size_t)b * HW + r] = predict(sv1[0], sv2[0]);
            if (out_size >= 2 * BATCH * HW)
                out[(size_t)BATCH * HW + (size_t)b * HW + r] = (float)si1[0];
        }
        __syncthreads();
    }
}

// ---------------------------------------------------------------------------
extern "C" void kernel_launch(void* const* d_in, const int* in_sizes, int n_in,
                              void* d_out, int out_size) {
    const float* x   = (const float*)d_in[0];
    float*       out = (float*)d_out;

    convert_norms_kernel<<<BATCH * HW / 8, 256>>>(x);

    cudaFuncSetAttribute(fcm_pair_kernel,
                         cudaFuncAttributeMaxDynamicSharedMemorySize, TOTSMEM);
    dim3 grid(NPAIR, BATCH);
    fcm_pair_kernel<<<grid, 512, TOTSMEM>>>();

    merge_refine_kernel<<<BATCH * HW / 8, 256>>>(x, out, out_size);
    fallback_kernel<<<256, 256>>>(x, out, out_size);
}

// round 7
// speedup vs baseline: 3.5651x; 1.3223x over previous
#include <cuda_runtime.h>
#include <cuda_bf16.h>
#include <cstdint>
#include <float.h>
#include <math.h>

#define BATCH 4
#define HW    4096
#define CDIM  256
#define NSTRIP 32
#define NPAIR  528
#define EPSQ  1e-9f
#define TLC   0.6f
#define LC    2.0f
#define MARGIN 0.75f
#define SROWB 144                 // bf16 staging row stride (128B data + 16B pad)
#define TENB  (128 * SROWB)
#define STAGEB (2 * TENB)
#define TOTSMEM (2 * STAGEB)      // 73728 B (Dt 64KB aliases this)
#define DPW   128                 // D-tile words per row (XOR-swizzled blocks)

// static device scratch
__device__ __nv_bfloat16 g_xhi[BATCH * HW * CDIM];
__device__ float g_norms[BATCH * HW];
__device__ uint2 g_pc[(size_t)BATCH * HW * NSTRIP * 8];   // (valbits, col) sorted-8
__device__ int   g_flagcnt;
__device__ int   g_flaglist[BATCH * HW];

// ---------------------------------------------------------------------------
__device__ __forceinline__ uint32_t smem_u32(const void* p) {
    uint32_t a;
    asm("{ .reg .u64 t; cvta.to.shared.u64 t, %1; cvt.u32.u64 %0, t; }"
        : "=r"(a) : "l"(p));
    return a;
}
__device__ __forceinline__ void cp16(uint32_t dst, const void* src) {
    asm volatile("cp.async.cg.shared.global [%0], [%1], 16;" :: "r"(dst), "l"(src));
}
__device__ __forceinline__ void cp_commit() {
    asm volatile("cp.async.commit_group;" ::: "memory");
}
template <int N> __device__ __forceinline__ void cp_wait() {
    asm volatile("cp.async.wait_group %0;" :: "n"(N) : "memory");
}
__device__ __forceinline__ void ldsm_x4(uint32_t (&r)[4], uint32_t addr) {
    asm volatile("ldmatrix.sync.aligned.m8n8.x4.shared.b16 {%0,%1,%2,%3}, [%4];"
                 : "=r"(r[0]), "=r"(r[1]), "=r"(r[2]), "=r"(r[3]) : "r"(addr));
}
__device__ __forceinline__ uint32_t redux_min_u32(uint32_t v) {
    uint32_t r;
    asm volatile("redux.sync.min.u32 %0, %1, 0xffffffff;" : "=r"(r) : "r"(v));
    return r;
}
#define MMA16816(d, a, b0_, b1_)                                                 \
    asm volatile("mma.sync.aligned.m16n8k16.row.col.f32.bf16.bf16.f32 "          \
                 "{%0,%1,%2,%3}, {%4,%5,%6,%7}, {%8,%9}, {%0,%1,%2,%3};"         \
                 : "+f"((d)[0]), "+f"((d)[1]), "+f"((d)[2]), "+f"((d)[3])        \
                 : "r"((a)[0]), "r"((a)[1]), "r"((a)[2]), "r"((a)[3]),           \
                   "r"(b0_), "r"(b1_))

// swizzled D-tile word index for logical (row r, col c)
__device__ __forceinline__ int dsw(int r, int c) {
    return r * DPW + ((((c >> 2) ^ (r & 31)) << 2) | (c & 3));
}
__device__ __forceinline__ bool ltp(float av, int ai, float bv, int bi) {
    return (av < bv) || (av == bv && ai < bi);
}
__device__ __forceinline__ void ceu(uint32_t& va, uint32_t& ca,
                                    uint32_t& vb, uint32_t& cb) {
    if (va > vb || (va == vb && ca > cb)) {
        uint32_t t = va; va = vb; vb = t;
        t = ca; ca = cb; cb = t;
    }
}
__device__ __forceinline__ float predict(float m1, float m2) {
    float d1 = sqrtf(fmaxf(m1, 0.f) + EPSQ);
    float d2 = sqrtf(fmaxf(m2, 0.f) + EPSQ);
    float e  = expf(d1);
    return (d1 / d2 < TLC) ? 2.f / (1.f + e) : 2.f / (1.f + LC * e);
}

// ---------------------------------------------------------------------------
// Kernel 1: fused bf16 convert + fp32 row norms (one warp per row)
// ---------------------------------------------------------------------------
__global__ void convert_norms_kernel(const float* __restrict__ x) {
    if (blockIdx.x == 0 && threadIdx.x == 0) g_flagcnt = 0;
    int gw   = (blockIdx.x * blockDim.x + threadIdx.x) >> 5;
    int lane = threadIdx.x & 31;
    if (gw >= BATCH * HW) return;
    const float* xr = x + (size_t)gw * CDIM + lane * 8;
    float4 v0 = *(const float4*)xr;
    float4 v1 = *(const float4*)(xr + 4);
    float s = v0.x*v0.x + v0.y*v0.y + v0.z*v0.z + v0.w*v0.w
            + v1.x*v1.x + v1.y*v1.y + v1.z*v1.z + v1.w*v1.w;
    __nv_bfloat162 p0(__float2bfloat16(v0.x), __float2bfloat16(v0.y));
    __nv_bfloat162 p1(__float2bfloat16(v0.z), __float2bfloat16(v0.w));
    __nv_bfloat162 p2(__float2bfloat16(v1.x), __float2bfloat16(v1.y));
    __nv_bfloat162 p3(__float2bfloat16(v1.z), __float2bfloat16(v1.w));
    uint4 u;
    u.x = *(uint32_t*)&p0; u.y = *(uint32_t*)&p1;
    u.z = *(uint32_t*)&p2; u.w = *(uint32_t*)&p3;
    ((uint4*)g_xhi)[(size_t)gw * 32 + lane] = u;
    #pragma unroll
    for (int o = 16; o; o >>= 1) s += __shfl_xor_sync(0xffffffffu, s, o);
    if (lane == 0) g_norms[gw] = s;
}

// ---------------------------------------------------------------------------
// Kernel 2: single-pass bf16 Gram tile-pair + redux pop-min top-8 per row/col.
// ---------------------------------------------------------------------------
__global__ __launch_bounds__(512, 1)
void fcm_pair_kernel() {
    extern __shared__ __align__(16) char smem[];
    const uint32_t sbase = smem_u32(smem);

    const int tid  = threadIdx.x;
    const int lane = tid & 31;
    const int w    = tid >> 5;
    const int mw   = w >> 2;
    const int nw   = w & 3;
    const int b    = blockIdx.y;

    int p = blockIdx.x;
    int i = (int)((65.0f - sqrtf(4225.0f - 8.0f * (float)p)) * 0.5f);
    while ((i + 1) * (65 - (i + 1)) / 2 <= p) ++i;
    while (i * (65 - i) / 2 > p) --i;
    const int j = i + (p - i * (65 - i) / 2);
    const int row0 = i * 128, col0 = j * 128;
    const bool diag = (i == j);

    const __nv_bfloat16* xb = g_xhi + (size_t)b * HW * CDIM;
    const int lrow = ((lane >> 3) & 1) * 8 + (lane & 7);
    const int lkb  = (lane >> 4) * 16;

    auto stage = [&](int kc) {
        const uint32_t dst = sbase + (uint32_t)((kc & 1) * STAGEB);
        #pragma unroll
        for (int o = 0; o < 2; ++o) {
            int lin = tid + o * 512;
            int r = lin >> 3, gg = lin & 7;
            cp16(dst + (uint32_t)(r * SROWB + gg * 16),
                 xb + (size_t)(row0 + r) * CDIM + kc * 64 + gg * 8);
            cp16(dst + TENB + (uint32_t)(r * SROWB + gg * 16),
                 xb + (size_t)(col0 + r) * CDIM + kc * 64 + gg * 8);
        }
        cp_commit();
    };
    stage(0);

    float acc[2][4][4];
    #pragma unroll
    for (int mf = 0; mf < 2; ++mf)
        #pragma unroll
        for (int nf = 0; nf < 4; ++nf)
            #pragma unroll
            for (int e = 0; e < 4; ++e) acc[mf][nf][e] = 0.f;

    for (int kc = 0; kc < 4; ++kc) {
        cp_wait<0>();
        __syncthreads();
        if (kc < 3) stage(kc + 1);
        const uint32_t bb  = sbase + (uint32_t)((kc & 1) * STAGEB);
        const uint32_t ab  = bb + (uint32_t)((mw * 32 + lrow) * SROWB);
        const uint32_t bbs = bb + TENB + (uint32_t)((nw * 32 + lrow) * SROWB);
        #pragma unroll
        for (int ks = 0; ks < 4; ++ks) {
            const uint32_t kb = (uint32_t)(ks * 32 + lkb);
            uint32_t ah[2][4], bh[2][4];
            ldsm_x4(ah[0], ab + kb);
            ldsm_x4(ah[1], ab + 16 * SROWB + kb);
            ldsm_x4(bh[0], bbs + kb);
            ldsm_x4(bh[1], bbs + 16 * SROWB + kb);
            #pragma unroll
            for (int mf = 0; mf < 2; ++mf)
                #pragma unroll
                for (int nf = 0; nf < 4; ++nf)
                    MMA16816(acc[mf][nf], ah[mf],
                             bh[nf >> 1][nf & 1], bh[nf >> 1][(nf & 1) + 2]);
        }
    }
    __syncthreads();                 // ldsm done; alias smem as swizzled D-tile

    // ---- fp32 squared-distance tile into swizzled SMEM (conflict-free) ----
    float* Dt = (float*)smem;
    #pragma unroll
    for (int mf = 0; mf < 2; ++mf) {
        const int r0l = mw * 32 + mf * 16 + (lane >> 2);
        const float na0 = g_norms[b * HW + row0 + r0l];
        const float na1 = g_norms[b * HW + row0 + r0l + 8];
        const float* nbp = g_norms + b * HW + col0 + nw * 32 + (lane & 3) * 2;
        #pragma unroll
        for (int nf = 0; nf < 4; ++nf) {
            float2 nb = *(const float2*)(nbp + nf * 8);
            int cl = nw * 32 + nf * 8 + (lane & 3) * 2;
            float2 d0 = { na0 + nb.x - 2.f * acc[mf][nf][0],
                          na0 + nb.y - 2.f * acc[mf][nf][1] };
            float2 d1 = { na1 + nb.x - 2.f * acc[mf][nf][2],
                          na1 + nb.y - 2.f * acc[mf][nf][3] };
            *(float2*)&Dt[dsw(r0l, cl)]     = d0;
            *(float2*)&Dt[dsw(r0l + 8, cl)] = d1;
        }
    }
    __syncthreads();

    // ---- warp-per-task top-8 extraction via redux pop-min ----
    const int ntask = diag ? 128 : 256;
    for (int t = w; t < ntask; t += 16) {
        uint32_t v[4], ci[4];
        if (t < 128) {                                  // row task: row rr
            const int rr = t;
            const float4 dv =
                *(const float4*)&Dt[rr * DPW + ((lane ^ (rr & 31)) << 2)];
            const int cbase = col0 + lane * 4;
            v[0] = __float_as_uint(dv.x); ci[0] = cbase;
            v[1] = __float_as_uint(dv.y); ci[1] = cbase + 1;
            v[2] = __float_as_uint(dv.z); ci[2] = cbase + 2;
            v[3] = __float_as_uint(dv.w); ci[3] = cbase + 3;
            if (diag) {
                #pragma unroll
                for (int q = 0; q < 4; ++q)
                    if (lane * 4 + q == rr) { v[q] = 0xffffffffu; ci[q] = 0x7fffffff; }
            }
        } else {                                        // col task: col cc
            const int cc = t - 128;
            const int cb = cc >> 2, cq = cc & 3;
            #pragma unroll
            for (int q = 0; q < 4; ++q) {
                const int r = lane * 4 + q;
                v[q]  = __float_as_uint(Dt[r * DPW + (((cb ^ (r & 31)) << 2) | cq)]);
                ci[q] = row0 + r;
            }
        }
        // per-lane ascending sort of 4 (value, index)
        ceu(v[0], ci[0], v[1], ci[1]); ceu(v[2], ci[2], v[3], ci[3]);
        ceu(v[0], ci[0], v[2], ci[2]); ceu(v[1], ci[1], v[3], ci[3]);
        ceu(v[1], ci[1], v[2], ci[2]);

        uint32_t myv = 0, myc = 0;
        #pragma unroll
        for (int pp = 0; pp < 8; ++pp) {
            uint32_t gv = redux_min_u32(v[0]);
            uint32_t cx = (v[0] == gv) ? ci[0] : 0xffffffffu;
            uint32_t gi = redux_min_u32(cx);
            if (lane == pp) { myv = gv; myc = gi; }
            if (v[0] == gv && ci[0] == gi) {            // unique winner pops
                v[0] = v[1]; ci[0] = ci[1];
                v[1] = v[2]; ci[1] = ci[2];
                v[2] = v[3]; ci[2] = ci[3];
                v[3] = 0xffffffffu; ci[3] = 0x7fffffff;
            }
        }
        const int grow = (t < 128) ? (row0 + t) : (col0 + (t - 128));
        const int slot = (t < 128) ? j : i;
        if (lane < 8)
            g_pc[(((size_t)(b * HW + grow)) * NSTRIP + slot) * 8 + lane] =
                make_uint2(myv, myc);
    }
}

// ---------------------------------------------------------------------------
// Kernel 3: warp-per-row global merge (redux pop-min over 32 slot lists) +
// exact fp32 refinement of 8 candidates + margin flagging.
// ---------------------------------------------------------------------------
__global__ void merge_refine_kernel(const float* __restrict__ x,
                                    float* __restrict__ out, int out_size) {
    int gw   = (blockIdx.x * blockDim.x + threadIdx.x) >> 5;
    int lane = threadIdx.x & 31;
    if (gw >= BATCH * HW) return;
    const int b = gw >> 12, rl = gw & 4095;

    const uint2* src = g_pc + ((size_t)gw * NSTRIP + lane) * 8;
    uint32_t v[8], ci[8];
    #pragma unroll
    for (int k = 0; k < 8; ++k) { uint2 e = src[k]; v[k] = e.x; ci[k] = e.y; }

    uint32_t gvs[8], gis[8];
    #pragma unroll
    for (int pp = 0; pp < 8; ++pp) {
        uint32_t gv = redux_min_u32(v[0]);
        uint32_t cx = (v[0] == gv) ? ci[0] : 0xffffffffu;
        uint32_t gi = redux_min_u32(cx);
        gvs[pp] = gv; gis[pp] = gi;
        if (v[0] == gv && ci[0] == gi) {
            #pragma unroll
            for (int q = 0; q < 7; ++q) { v[q] = v[q + 1]; ci[q] = ci[q + 1]; }
            v[7] = 0xffffffffu; ci[7] = 0x7fffffff;
        }
    }

    // exact fp32 refinement of the 8 global candidates
    const float* xb = x + (size_t)b * HW * CDIM;
    const float* xr = xb + (size_t)rl * CDIM + lane * 8;
    float4 a0 = *(const float4*)xr;
    float4 a1 = *(const float4*)(xr + 4);
    const float nr = g_norms[b * HW + rl];

    float m1 = FLT_MAX, m2 = FLT_MAX; int j1 = 0, j2 = 0;
    #pragma unroll
    for (int k = 0; k < 8; ++k) {
        const int c = (int)gis[k];
        const float* xc = xb + (size_t)c * CDIM + lane * 8;
        float4 c0 = *(const float4*)xc;
        float4 c1 = *(const float4*)(xc + 4);
        float s = a0.x*c0.x + a0.y*c0.y + a0.z*c0.z + a0.w*c0.w
                + a1.x*c1.x + a1.y*c1.y + a1.z*c1.z + a1.w*c1.w;
        #pragma unroll
        for (int off = 16; off; off >>= 1) s += __shfl_xor_sync(0xffffffffu, s, off);
        float D = nr + g_norms[b * HW + c] - 2.f * s;
        if (ltp(D, c, m1, j1)) { m2 = m1; j2 = j1; m1 = D; j1 = c; }
        else if (ltp(D, c, m2, j2)) { m2 = D; j2 = c; }
    }

    if (lane == 0) {
        out[(size_t)b * HW + rl] = predict(m1, m2);
        if (out_size >= 2 * BATCH * HW)
            out[(size_t)BATCH * HW + (size_t)b * HW + rl] = (float)j1;
        // non-candidates have D_bf16 >= v8  =>  D_exact >= v8 - MARGIN
        if (m2 > __uint_as_float(gvs[7]) - MARGIN) {
            int fi = atomicAdd(&g_flagcnt, 1);
            g_flaglist[fi] = gw;
        }
    }
}

// ---------------------------------------------------------------------------
// Kernel 4: exact full-row rescan for flagged rows (expected ~0 rows).
// ---------------------------------------------------------------------------
__global__ void fallback_kernel(const float* __restrict__ x,
                                float* __restrict__ out, int out_size) {
    __shared__ float sv1[256], sv2[256];
    __shared__ int   si1[256];
    const int n = g_flagcnt;
    for (int fi = blockIdx.x; fi < n; fi += gridDim.x) {
        const int rowg = g_flaglist[fi];
        const int b = rowg >> 12, r = rowg & 4095;
        const float* xb = x + (size_t)b * HW * CDIM;
        const float* xr = xb + (size_t)r * CDIM;
        const float  nr = g_norms[rowg];
        float v1 = FLT_MAX, v2 = FLT_MAX; int i1 = 0x7fffffff;
        for (int c = threadIdx.x; c < HW; c += 256) {
            if (c == r) continue;
            const float4* xc = (const float4*)(xb + (size_t)c * CDIM);
            float s = 0.f;
            #pragma unroll
            for (int d = 0; d < 64; ++d) {
                float4 va = ((const float4*)xr)[d];
                float4 vb = xc[d];
                s += va.x*vb.x + va.y*vb.y + va.z*vb.z + va.w*vb.w;
            }
            float D = nr + g_norms[b * HW + c] - 2.f * s;
            if (ltp(D, c, v1, i1)) { v2 = v1; v1 = D; i1 = c; }
            else if (D < v2) { v2 = D; }
        }
        sv1[threadIdx.x] = v1; sv2[threadIdx.x] = v2; si1[threadIdx.x] = i1;
        __syncthreads();
        for (int off = 128; off; off >>= 1) {
            if (threadIdx.x < off) {
                float b1 = sv1[threadIdx.x + off], b2 = sv2[threadIdx.x + off];
                int   bi = si1[threadIdx.x + off];
                float a1v = sv1[threadIdx.x]; int a1i = si1[threadIdx.x];
                if (ltp(b1, bi, a1v, a1i)) {
                    sv2[threadIdx.x] = fminf(a1v, b2);
                    sv1[threadIdx.x] = b1; si1[threadIdx.x] = bi;
                } else {
                    sv2[threadIdx.x] = fminf(sv2[threadIdx.x], b1);
                }
            }
            __syncthreads();
        }
        if (threadIdx.x == 0) {
            out[(size_t)b * HW + r] = predict(sv1[0], sv2[0]);
            if (out_size >= 2 * BATCH * HW)
                out[(size_t)BATCH * HW + (size_t)b * HW + r] = (float)si1[0];
        }
        __syncthreads();
    }
}

// ---------------------------------------------------------------------------
extern "C" void kernel_launch(void* const* d_in, const int* in_sizes, int n_in,
                              void* d_out, int out_size) {
    const float* x   = (const float*)d_in[0];
    float*       out = (float*)d_out;

    convert_norms_kernel<<<BATCH * HW / 8, 256>>>(x);

    cudaFuncSetAttribute(fcm_pair_kernel,
                         cudaFuncAttributeMaxDynamicSharedMemorySize, TOTSMEM);
    dim3 grid(NPAIR, BATCH);
    fcm_pair_kernel<<<grid, 512, TOTSMEM>>>();

    merge_refine_kernel<<<BATCH * HW / 8, 256>>>(x, out, out_size);
    fallback_kernel<<<256, 256>>>(x, out, out_size);
}

// round 8
// speedup vs baseline: 4.6610x; 1.3074x over previous
#include <cuda_runtime.h>
#include <cuda_bf16.h>
#include <cstdint>
#include <float.h>
#include <math.h>

#define BATCH 4
#define HW    4096
#define CDIM  256
#define NSTRIP 32
#define NPAIR  528
#define EPSQ  1e-9f
#define TLC   0.6f
#define LC    2.0f
#define MARGIN 0.75f
#define SROWB 144                 // bf16 staging row stride (128B data + 16B pad)
#define TENB  (128 * SROWB)
#define STAGEB (2 * TENB)
#define TOTSMEM (2 * STAGEB)      // 73728 B (Dt 64KB aliases this)
#define DPW   128                 // D-tile words per row (XOR-swizzled blocks)

// static device scratch
__device__ __nv_bfloat16 g_xhi[BATCH * HW * CDIM];
__device__ float g_norms[BATCH * HW];
__device__ uint2 g_pc[(size_t)BATCH * HW * NSTRIP * 4];   // (valbits, col) sorted-4
__device__ int   g_flagcnt;
__device__ int   g_flaglist[BATCH * HW];

// ---------------------------------------------------------------------------
__device__ __forceinline__ uint32_t smem_u32(const void* p) {
    uint32_t a;
    asm("{ .reg .u64 t; cvta.to.shared.u64 t, %1; cvt.u32.u64 %0, t; }"
        : "=r"(a) : "l"(p));
    return a;
}
__device__ __forceinline__ void cp16(uint32_t dst, const void* src) {
    asm volatile("cp.async.cg.shared.global [%0], [%1], 16;" :: "r"(dst), "l"(src));
}
__device__ __forceinline__ void cp_commit() {
    asm volatile("cp.async.commit_group;" ::: "memory");
}
template <int N> __device__ __forceinline__ void cp_wait() {
    asm volatile("cp.async.wait_group %0;" :: "n"(N) : "memory");
}
__device__ __forceinline__ void ldsm_x4(uint32_t (&r)[4], uint32_t addr) {
    asm volatile("ldmatrix.sync.aligned.m8n8.x4.shared.b16 {%0,%1,%2,%3}, [%4];"
                 : "=r"(r[0]), "=r"(r[1]), "=r"(r[2]), "=r"(r[3]) : "r"(addr));
}
__device__ __forceinline__ uint32_t redux_min_u32(uint32_t v) {
    uint32_t r;
    asm volatile("redux.sync.min.u32 %0, %1, 0xffffffff;" : "=r"(r) : "r"(v));
    return r;
}
#define MMA16816(d, a, b0_, b1_)                                                 \
    asm volatile("mma.sync.aligned.m16n8k16.row.col.f32.bf16.bf16.f32 "          \
                 "{%0,%1,%2,%3}, {%4,%5,%6,%7}, {%8,%9}, {%0,%1,%2,%3};"         \
                 : "+f"((d)[0]), "+f"((d)[1]), "+f"((d)[2]), "+f"((d)[3])        \
                 : "r"((a)[0]), "r"((a)[1]), "r"((a)[2]), "r"((a)[3]),           \
                   "r"(b0_), "r"(b1_))

// swizzled D-tile word index for logical (row r, col c)
__device__ __forceinline__ int dsw(int r, int c) {
    return r * DPW + ((((c >> 2) ^ (r & 31)) << 2) | (c & 3));
}
__device__ __forceinline__ bool ltp(float av, int ai, float bv, int bi) {
    return (av < bv) || (av == bv && ai < bi);
}
__device__ __forceinline__ void ceu(uint32_t& va, uint32_t& ca,
                                    uint32_t& vb, uint32_t& cb) {
    if (va > vb || (va == vb && ca > cb)) {
        uint32_t t = va; va = vb; vb = t;
        t = ca; ca = cb; cb = t;
    }
}
__device__ __forceinline__ float predict(float m1, float m2) {
    float d1 = sqrtf(fmaxf(m1, 0.f) + EPSQ);
    float d2 = sqrtf(fmaxf(m2, 0.f) + EPSQ);
    float e  = expf(d1);
    return (d1 / d2 < TLC) ? 2.f / (1.f + e) : 2.f / (1.f + LC * e);
}

// ---------------------------------------------------------------------------
// Kernel 1: fused bf16 convert + fp32 row norms (one warp per row)
// ---------------------------------------------------------------------------
__global__ void convert_norms_kernel(const float* __restrict__ x) {
    if (blockIdx.x == 0 && threadIdx.x == 0) g_flagcnt = 0;
    int gw   = (blockIdx.x * blockDim.x + threadIdx.x) >> 5;
    int lane = threadIdx.x & 31;
    if (gw >= BATCH * HW) return;
    const float* xr = x + (size_t)gw * CDIM + lane * 8;
    float4 v0 = *(const float4*)xr;
    float4 v1 = *(const float4*)(xr + 4);
    float s = v0.x*v0.x + v0.y*v0.y + v0.z*v0.z + v0.w*v0.w
            + v1.x*v1.x + v1.y*v1.y + v1.z*v1.z + v1.w*v1.w;
    __nv_bfloat162 p0(__float2bfloat16(v0.x), __float2bfloat16(v0.y));
    __nv_bfloat162 p1(__float2bfloat16(v0.z), __float2bfloat16(v0.w));
    __nv_bfloat162 p2(__float2bfloat16(v1.x), __float2bfloat16(v1.y));
    __nv_bfloat162 p3(__float2bfloat16(v1.z), __float2bfloat16(v1.w));
    uint4 u;
    u.x = *(uint32_t*)&p0; u.y = *(uint32_t*)&p1;
    u.z = *(uint32_t*)&p2; u.w = *(uint32_t*)&p3;
    ((uint4*)g_xhi)[(size_t)gw * 32 + lane] = u;
    #pragma unroll
    for (int o = 16; o; o >>= 1) s += __shfl_xor_sync(0xffffffffu, s, o);
    if (lane == 0) g_norms[gw] = s;
}

// ---------------------------------------------------------------------------
// Kernel 2: single-pass bf16 Gram tile-pair + top-4 per row/col via
// redux pop-min with 2-task ILP.
// ---------------------------------------------------------------------------
__global__ __launch_bounds__(512, 1)
void fcm_pair_kernel() {
    extern __shared__ __align__(16) char smem[];
    const uint32_t sbase = smem_u32(smem);

    const int tid  = threadIdx.x;
    const int lane = tid & 31;
    const int w    = tid >> 5;
    const int mw   = w >> 2;
    const int nw   = w & 3;
    const int b    = blockIdx.y;

    int p = blockIdx.x;
    int i = (int)((65.0f - sqrtf(4225.0f - 8.0f * (float)p)) * 0.5f);
    while ((i + 1) * (65 - (i + 1)) / 2 <= p) ++i;
    while (i * (65 - i) / 2 > p) --i;
    const int j = i + (p - i * (65 - i) / 2);
    const int row0 = i * 128, col0 = j * 128;
    const bool diag = (i == j);

    const __nv_bfloat16* xb = g_xhi + (size_t)b * HW * CDIM;
    const int lrow = ((lane >> 3) & 1) * 8 + (lane & 7);
    const int lkb  = (lane >> 4) * 16;

    auto stage = [&](int kc) {
        const uint32_t dst = sbase + (uint32_t)((kc & 1) * STAGEB);
        #pragma unroll
        for (int o = 0; o < 2; ++o) {
            int lin = tid + o * 512;
            int r = lin >> 3, gg = lin & 7;
            cp16(dst + (uint32_t)(r * SROWB + gg * 16),
                 xb + (size_t)(row0 + r) * CDIM + kc * 64 + gg * 8);
            cp16(dst + TENB + (uint32_t)(r * SROWB + gg * 16),
                 xb + (size_t)(col0 + r) * CDIM + kc * 64 + gg * 8);
        }
        cp_commit();
    };
    stage(0);

    float acc[2][4][4];
    #pragma unroll
    for (int mf = 0; mf < 2; ++mf)
        #pragma unroll
        for (int nf = 0; nf < 4; ++nf)
            #pragma unroll
            for (int e = 0; e < 4; ++e) acc[mf][nf][e] = 0.f;

    for (int kc = 0; kc < 4; ++kc) {
        cp_wait<0>();
        __syncthreads();
        if (kc < 3) stage(kc + 1);
        const uint32_t bb  = sbase + (uint32_t)((kc & 1) * STAGEB);
        const uint32_t ab  = bb + (uint32_t)((mw * 32 + lrow) * SROWB);
        const uint32_t bbs = bb + TENB + (uint32_t)((nw * 32 + lrow) * SROWB);
        #pragma unroll
        for (int ks = 0; ks < 4; ++ks) {
            const uint32_t kb = (uint32_t)(ks * 32 + lkb);
            uint32_t ah[2][4], bh[2][4];
            ldsm_x4(ah[0], ab + kb);
            ldsm_x4(ah[1], ab + 16 * SROWB + kb);
            ldsm_x4(bh[0], bbs + kb);
            ldsm_x4(bh[1], bbs + 16 * SROWB + kb);
            #pragma unroll
            for (int mf = 0; mf < 2; ++mf)
                #pragma unroll
                for (int nf = 0; nf < 4; ++nf)
                    MMA16816(acc[mf][nf], ah[mf],
                             bh[nf >> 1][nf & 1], bh[nf >> 1][(nf & 1) + 2]);
        }
    }
    __syncthreads();                 // ldsm done; alias smem as swizzled D-tile

    // ---- fp32 squared-distance tile into swizzled SMEM ----
    float* Dt = (float*)smem;
    #pragma unroll
    for (int mf = 0; mf < 2; ++mf) {
        const int r0l = mw * 32 + mf * 16 + (lane >> 2);
        const float na0 = g_norms[b * HW + row0 + r0l];
        const float na1 = g_norms[b * HW + row0 + r0l + 8];
        const float* nbp = g_norms + b * HW + col0 + nw * 32 + (lane & 3) * 2;
        #pragma unroll
        for (int nf = 0; nf < 4; ++nf) {
            float2 nb = *(const float2*)(nbp + nf * 8);
            int cl = nw * 32 + nf * 8 + (lane & 3) * 2;
            float2 d0 = { na0 + nb.x - 2.f * acc[mf][nf][0],
                          na0 + nb.y - 2.f * acc[mf][nf][1] };
            float2 d1 = { na1 + nb.x - 2.f * acc[mf][nf][2],
                          na1 + nb.y - 2.f * acc[mf][nf][3] };
            *(float2*)&Dt[dsw(r0l, cl)]     = d0;
            *(float2*)&Dt[dsw(r0l + 8, cl)] = d1;
        }
    }
    __syncthreads();

    // ---- top-4 extraction: 2 tasks per iteration, interleaved pop-min ----
    const int ntask = diag ? 128 : 256;
    for (int t0 = w; t0 < ntask; t0 += 32) {
        uint32_t v[2][4], ci[2][4];
        #pragma unroll
        for (int u = 0; u < 2; ++u) {
            const int t = t0 + 16 * u;
            if (t < 128) {                              // row task
                const int rr = t;
                const float4 dv =
                    *(const float4*)&Dt[rr * DPW + ((lane ^ (rr & 31)) << 2)];
                const int cbase = col0 + lane * 4;
                v[u][0] = __float_as_uint(dv.x); ci[u][0] = cbase;
                v[u][1] = __float_as_uint(dv.y); ci[u][1] = cbase + 1;
                v[u][2] = __float_as_uint(dv.z); ci[u][2] = cbase + 2;
                v[u][3] = __float_as_uint(dv.w); ci[u][3] = cbase + 3;
                if (diag) {
                    #pragma unroll
                    for (int q = 0; q < 4; ++q)
                        if (lane * 4 + q == rr) {
                            v[u][q] = 0xffffffffu; ci[u][q] = 0x7fffffff;
                        }
                }
            } else {                                    // col task
                const int cc = t - 128;
                const int cb = cc >> 2, cq = cc & 3;
                #pragma unroll
                for (int q = 0; q < 4; ++q) {
                    const int r = lane + 32 * q;
                    v[u][q]  = __float_as_uint(
                        Dt[r * DPW + (((cb ^ (r & 31)) << 2) | cq)]);
                    ci[u][q] = row0 + r;
                }
            }
            ceu(v[u][0], ci[u][0], v[u][1], ci[u][1]);
            ceu(v[u][2], ci[u][2], v[u][3], ci[u][3]);
            ceu(v[u][0], ci[u][0], v[u][2], ci[u][2]);
            ceu(v[u][1], ci[u][1], v[u][3], ci[u][3]);
            ceu(v[u][1], ci[u][1], v[u][2], ci[u][2]);
        }

        uint32_t myv[2], myc[2];
        #pragma unroll
        for (int pp = 0; pp < 4; ++pp) {
            uint32_t gv0 = redux_min_u32(v[0][0]);
            uint32_t gv1 = redux_min_u32(v[1][0]);
            uint32_t cx0 = (v[0][0] == gv0) ? ci[0][0] : 0xffffffffu;
            uint32_t cx1 = (v[1][0] == gv1) ? ci[1][0] : 0xffffffffu;
            uint32_t gi0 = redux_min_u32(cx0);
            uint32_t gi1 = redux_min_u32(cx1);
            if (lane == pp) { myv[0] = gv0; myc[0] = gi0;
                              myv[1] = gv1; myc[1] = gi1; }
            if (v[0][0] == gv0 && ci[0][0] == gi0) {
                v[0][0] = v[0][1]; ci[0][0] = ci[0][1];
                v[0][1] = v[0][2]; ci[0][1] = ci[0][2];
                v[0][2] = v[0][3]; ci[0][2] = ci[0][3];
                v[0][3] = 0xffffffffu; ci[0][3] = 0x7fffffff;
            }
            if (v[1][0] == gv1 && ci[1][0] == gi1) {
                v[1][0] = v[1][1]; ci[1][0] = ci[1][1];
                v[1][1] = v[1][2]; ci[1][1] = ci[1][2];
                v[1][2] = v[1][3]; ci[1][2] = ci[1][3];
                v[1][3] = 0xffffffffu; ci[1][3] = 0x7fffffff;
            }
        }
        if (lane < 4) {
            #pragma unroll
            for (int u = 0; u < 2; ++u) {
                const int t = t0 + 16 * u;
                const int grow = (t < 128) ? (row0 + t) : (col0 + (t - 128));
                const int slot = (t < 128) ? j : i;
                g_pc[(((size_t)(b * HW + grow)) * NSTRIP + slot) * 4 + lane] =
                    make_uint2(myv[u], myc[u]);
            }
        }
    }
}

// ---------------------------------------------------------------------------
// Kernel 3: warp-per-row merge of 32 slot top-4s (redux pop-min) + exact
// fp32 refinement of 8 candidates + margin flagging vs min(B1, v8c).
// ---------------------------------------------------------------------------
__global__ void merge_refine_kernel(const float* __restrict__ x,
                                    float* __restrict__ out, int out_size) {
    int gw   = (blockIdx.x * blockDim.x + threadIdx.x) >> 5;
    int lane = threadIdx.x & 31;
    if (gw >= BATCH * HW) return;
    const int b = gw >> 12, rl = gw & 4095;

    const uint2* src = g_pc + ((size_t)gw * NSTRIP + lane) * 4;
    uint32_t v[4], ci[4];
    #pragma unroll
    for (int k = 0; k < 4; ++k) { uint2 e = src[k]; v[k] = e.x; ci[k] = e.y; }

    // B1 = min over tiles of that tile's 4th-smallest (screen bound)
    const uint32_t b1 = redux_min_u32(v[3]);

    uint32_t gvs[8], gis[8];
    #pragma unroll
    for (int pp = 0; pp < 8; ++pp) {
        uint32_t gv = redux_min_u32(v[0]);
        uint32_t cx = (v[0] == gv) ? ci[0] : 0xffffffffu;
        uint32_t gi = redux_min_u32(cx);
        gvs[pp] = gv; gis[pp] = gi;
        if (v[0] == gv && ci[0] == gi) {
            v[0] = v[1]; ci[0] = ci[1];
            v[1] = v[2]; ci[1] = ci[2];
            v[2] = v[3]; ci[2] = ci[3];
            v[3] = 0xffffffffu; ci[3] = 0x7fffffff;
        }
    }

    // exact fp32 refinement of the 8 global candidates
    const float* xb = x + (size_t)b * HW * CDIM;
    const float* xr = xb + (size_t)rl * CDIM + lane * 8;
    float4 a0 = *(const float4*)xr;
    float4 a1 = *(const float4*)(xr + 4);
    const float nr = g_norms[b * HW + rl];

    float m1 = FLT_MAX, m2 = FLT_MAX; int j1 = 0, j2 = 0;
    #pragma unroll
    for (int k = 0; k < 8; ++k) {
        const int c = (int)gis[k];
        const float* xc = xb + (size_t)c * CDIM + lane * 8;
        float4 c0 = *(const float4*)xc;
        float4 c1 = *(const float4*)(xc + 4);
        float s = a0.x*c0.x + a0.y*c0.y + a0.z*c0.z + a0.w*c0.w
                + a1.x*c1.x + a1.y*c1.y + a1.z*c1.z + a1.w*c1.w;
        #pragma unroll
        for (int off = 16; off; off >>= 1) s += __shfl_xor_sync(0xffffffffu, s, off);
        float D = nr + g_norms[b * HW + c] - 2.f * s;
        if (ltp(D, c, m1, j1)) { m2 = m1; j2 = j1; m1 = D; j1 = c; }
        else if (ltp(D, c, m2, j2)) { m2 = D; j2 = c; }
    }

    if (lane == 0) {
        out[(size_t)b * HW + rl] = predict(m1, m2);
        if (out_size >= 2 * BATCH * HW)
            out[(size_t)BATCH * HW + (size_t)b * HW + rl] = (float)j1;
        // non-candidates: D_bf16 >= min(tile v4) = B1; unrefined candidates:
        // D_bf16 >= gvs[7]. Either way D_exact >= bound - MARGIN.
        float bound = fminf(__uint_as_float(b1), __uint_as_float(gvs[7]));
        if (m2 > bound - MARGIN) {
            int fi = atomicAdd(&g_flagcnt, 1);
            g_flaglist[fi] = gw;
        }
    }
}

// ---------------------------------------------------------------------------
// Kernel 4: exact full-row rescan for flagged rows (expected ~0 rows).
// ---------------------------------------------------------------------------
__global__ void fallback_kernel(const float* __restrict__ x,
                                float* __restrict__ out, int out_size) {
    __shared__ float sv1[256], sv2[256];
    __shared__ int   si1[256];
    const int n = g_flagcnt;
    for (int fi = blockIdx.x; fi < n; fi += gridDim.x) {
        const int rowg = g_flaglist[fi];
        const int b = rowg >> 12, r = rowg & 4095;
        const float* xb = x + (size_t)b * HW * CDIM;
        const float* xr = xb + (size_t)r * CDIM;
        const float  nr = g_norms[rowg];
        float v1 = FLT_MAX, v2 = FLT_MAX; int i1 = 0x7fffffff;
        for (int c = threadIdx.x; c < HW; c += 256) {
            if (c == r) continue;
            const float4* xc = (const float4*)(xb + (size_t)c * CDIM);
            float s = 0.f;
            #pragma unroll
            for (int d = 0; d < 64; ++d) {
                float4 va = ((const float4*)xr)[d];
                float4 vb = xc[d];
                s += va.x*vb.x + va.y*vb.y + va.z*vb.z + va.w*vb.w;
            }
            float D = nr + g_norms[b * HW + c] - 2.f * s;
            if (ltp(D, c, v1, i1)) { v2 = v1; v1 = D; i1 = c; }
            else if (D < v2) { v2 = D; }
        }
        sv1[threadIdx.x] = v1; sv2[threadIdx.x] = v2; si1[threadIdx.x] = i1;
        __syncthreads();
        for (int off = 128; off; off >>= 1) {
            if (threadIdx.x < off) {
                float b1 = sv1[threadIdx.x + off], b2 = sv2[threadIdx.x + off];
                int   bi = si1[threadIdx.x + off];
                float a1v = sv1[threadIdx.x]; int a1i = si1[threadIdx.x];
                if (ltp(b1, bi, a1v, a1i)) {
                    sv2[threadIdx.x] = fminf(a1v, b2);
                    sv1[threadIdx.x] = b1; si1[threadIdx.x] = bi;
                } else {
                    sv2[threadIdx.x] = fminf(sv2[threadIdx.x], b1);
                }
            }
            __syncthreads();
        }
        if (threadIdx.x == 0) {
            out[(size_t)b * HW + r] = predict(sv1[0], sv2[0]);
            if (out_size >= 2 * BATCH * HW)
                out[(size_t)BATCH * HW + (size_t)b * HW + r] = (float)si1[0];
        }
        __syncthreads();
    }
}

// ---------------------------------------------------------------------------
extern "C" void kernel_launch(void* const* d_in, const int* in_sizes, int n_in,
                              void* d_out, int out_size) {
    const float* x   = (const float*)d_in[0];
    float*       out = (float*)d_out;

    convert_norms_kernel<<<BATCH * HW / 8, 256>>>(x);

    cudaFuncSetAttribute(fcm_pair_kernel,
                         cudaFuncAttributeMaxDynamicSharedMemorySize, TOTSMEM);
    dim3 grid(NPAIR, BATCH);
    fcm_pair_kernel<<<grid, 512, TOTSMEM>>>();

    merge_refine_kernel<<<BATCH * HW / 8, 256>>>(x, out, out_size);
    fallback_kernel<<<256, 256>>>(x, out, out_size);
}

// round 9
// speedup vs baseline: 5.9554x; 1.2777x over previous
#include <cuda_runtime.h>
#include <cuda_bf16.h>
#include <cstdint>
#include <float.h>
#include <math.h>

#define BATCH 4
#define HW    4096
#define CDIM  256
#define NSTRIP 32
#define NPAIR  528
#define EPSQ  1e-9f
#define TLC   0.6f
#define LC    2.0f
#define MARGIN 0.75f
#define SROWB 144                 // bf16 staging row stride (128B data + 16B pad)
#define TENB  (128 * SROWB)
#define STAGEB (2 * TENB)
#define TOTSMEM (2 * STAGEB)      // 73728 B (Dt 64KB aliases this)
#define DPW   128                 // D-tile words per row (XOR-swizzled blocks)

// static device scratch
__device__ __nv_bfloat16 g_xhi[BATCH * HW * CDIM];
__device__ float    g_norms[BATCH * HW];
__device__ uint32_t g_pc[(size_t)BATCH * HW * NSTRIP * 4];  // packed (val25|idx7)
__device__ int      g_flagcnt;
__device__ int      g_flaglist[BATCH * HW];

// ---------------------------------------------------------------------------
__device__ __forceinline__ uint32_t smem_u32(const void* p) {
    uint32_t a;
    asm("{ .reg .u64 t; cvta.to.shared.u64 t, %1; cvt.u32.u64 %0, t; }"
        : "=r"(a) : "l"(p));
    return a;
}
__device__ __forceinline__ void cp16(uint32_t dst, const void* src) {
    asm volatile("cp.async.cg.shared.global [%0], [%1], 16;" :: "r"(dst), "l"(src));
}
__device__ __forceinline__ void cp_commit() {
    asm volatile("cp.async.commit_group;" ::: "memory");
}
template <int N> __device__ __forceinline__ void cp_wait() {
    asm volatile("cp.async.wait_group %0;" :: "n"(N) : "memory");
}
__device__ __forceinline__ void ldsm_x4(uint32_t (&r)[4], uint32_t addr) {
    asm volatile("ldmatrix.sync.aligned.m8n8.x4.shared.b16 {%0,%1,%2,%3}, [%4];"
                 : "=r"(r[0]), "=r"(r[1]), "=r"(r[2]), "=r"(r[3]) : "r"(addr));
}
__device__ __forceinline__ uint32_t redux_min_u32(uint32_t v) {
    uint32_t r;
    asm volatile("redux.sync.min.u32 %0, %1, 0xffffffff;" : "=r"(r) : "r"(v));
    return r;
}
#define MMA16816(d, a, b0_, b1_)                                                 \
    asm volatile("mma.sync.aligned.m16n8k16.row.col.f32.bf16.bf16.f32 "          \
                 "{%0,%1,%2,%3}, {%4,%5,%6,%7}, {%8,%9}, {%0,%1,%2,%3};"         \
                 : "+f"((d)[0]), "+f"((d)[1]), "+f"((d)[2]), "+f"((d)[3])        \
                 : "r"((a)[0]), "r"((a)[1]), "r"((a)[2]), "r"((a)[3]),           \
                   "r"(b0_), "r"(b1_))

// swizzled D-tile word index for logical (row r, col c)
__device__ __forceinline__ int dsw(int r, int c) {
    return r * DPW + ((((c >> 2) ^ (r & 31)) << 2) | (c & 3));
}
__device__ __forceinline__ bool ltp(float av, int ai, float bv, int bi) {
    return (av < bv) || (av == bv && ai < bi);
}
// ascending compare-exchange on packed keys (2 instr: min + max)
__device__ __forceinline__ void ceu(uint32_t& a, uint32_t& b) {
    uint32_t mn = min(a, b);
    b = max(a, b);
    a = mn;
}
__device__ __forceinline__ void sort4u(uint32_t (&k)[4]) {
    ceu(k[0], k[1]); ceu(k[2], k[3]);
    ceu(k[0], k[2]); ceu(k[1], k[3]);
    ceu(k[1], k[2]);
}
__device__ __forceinline__ float predict(float m1, float m2) {
    float d1 = sqrtf(fmaxf(m1, 0.f) + EPSQ);
    float d2 = sqrtf(fmaxf(m2, 0.f) + EPSQ);
    float e  = expf(d1);
    return (d1 / d2 < TLC) ? 2.f / (1.f + e) : 2.f / (1.f + LC * e);
}

// ---------------------------------------------------------------------------
// Kernel 1: fused bf16 convert + fp32 row norms (one warp per row)
// ---------------------------------------------------------------------------
__global__ void convert_norms_kernel(const float* __restrict__ x) {
    if (blockIdx.x == 0 && threadIdx.x == 0) g_flagcnt = 0;
    int gw   = (blockIdx.x * blockDim.x + threadIdx.x) >> 5;
    int lane = threadIdx.x & 31;
    if (gw >= BATCH * HW) return;
    const float* xr = x + (size_t)gw * CDIM + lane * 8;
    float4 v0 = *(const float4*)xr;
    float4 v1 = *(const float4*)(xr + 4);
    float s = v0.x*v0.x + v0.y*v0.y + v0.z*v0.z + v0.w*v0.w
            + v1.x*v1.x + v1.y*v1.y + v1.z*v1.z + v1.w*v1.w;
    __nv_bfloat162 p0(__float2bfloat16(v0.x), __float2bfloat16(v0.y));
    __nv_bfloat162 p1(__float2bfloat16(v0.z), __float2bfloat16(v0.w));
    __nv_bfloat162 p2(__float2bfloat16(v1.x), __float2bfloat16(v1.y));
    __nv_bfloat162 p3(__float2bfloat16(v1.z), __float2bfloat16(v1.w));
    uint4 u;
    u.x = *(uint32_t*)&p0; u.y = *(uint32_t*)&p1;
    u.z = *(uint32_t*)&p2; u.w = *(uint32_t*)&p3;
    ((uint4*)g_xhi)[(size_t)gw * 32 + lane] = u;
    #pragma unroll
    for (int o = 16; o; o >>= 1) s += __shfl_xor_sync(0xffffffffu, s, o);
    if (lane == 0) g_norms[gw] = s;
}

// ---------------------------------------------------------------------------
// Kernel 2: single-pass bf16 Gram tile-pair + packed-key top-4 per row/col
// (one redux per pop, 2-task ILP).
// ---------------------------------------------------------------------------
__global__ __launch_bounds__(512, 1)
void fcm_pair_kernel() {
    extern __shared__ __align__(16) char smem[];
    const uint32_t sbase = smem_u32(smem);

    const int tid  = threadIdx.x;
    const int lane = tid & 31;
    const int w    = tid >> 5;
    const int mw   = w >> 2;
    const int nw   = w & 3;
    const int b    = blockIdx.y;

    int p = blockIdx.x;
    int i = (int)((65.0f - sqrtf(4225.0f - 8.0f * (float)p)) * 0.5f);
    while ((i + 1) * (65 - (i + 1)) / 2 <= p) ++i;
    while (i * (65 - i) / 2 > p) --i;
    const int j = i + (p - i * (65 - i) / 2);
    const int row0 = i * 128, col0 = j * 128;
    const bool diag = (i == j);

    const __nv_bfloat16* xb = g_xhi + (size_t)b * HW * CDIM;
    const int lrow = ((lane >> 3) & 1) * 8 + (lane & 7);
    const int lkb  = (lane >> 4) * 16;

    auto stage = [&](int kc) {
        const uint32_t dst = sbase + (uint32_t)((kc & 1) * STAGEB);
        #pragma unroll
        for (int o = 0; o < 2; ++o) {
            int lin = tid + o * 512;
            int r = lin >> 3, gg = lin & 7;
            cp16(dst + (uint32_t)(r * SROWB + gg * 16),
                 xb + (size_t)(row0 + r) * CDIM + kc * 64 + gg * 8);
            cp16(dst + TENB + (uint32_t)(r * SROWB + gg * 16),
                 xb + (size_t)(col0 + r) * CDIM + kc * 64 + gg * 8);
        }
        cp_commit();
    };
    stage(0);

    float acc[2][4][4];
    #pragma unroll
    for (int mf = 0; mf < 2; ++mf)
        #pragma unroll
        for (int nf = 0; nf < 4; ++nf)
            #pragma unroll
            for (int e = 0; e < 4; ++e) acc[mf][nf][e] = 0.f;

    for (int kc = 0; kc < 4; ++kc) {
        cp_wait<0>();
        __syncthreads();
        if (kc < 3) stage(kc + 1);
        const uint32_t bb  = sbase + (uint32_t)((kc & 1) * STAGEB);
        const uint32_t ab  = bb + (uint32_t)((mw * 32 + lrow) * SROWB);
        const uint32_t bbs = bb + TENB + (uint32_t)((nw * 32 + lrow) * SROWB);
        #pragma unroll
        for (int ks = 0; ks < 4; ++ks) {
            const uint32_t kb = (uint32_t)(ks * 32 + lkb);
            uint32_t ah[2][4], bh[2][4];
            ldsm_x4(ah[0], ab + kb);
            ldsm_x4(ah[1], ab + 16 * SROWB + kb);
            ldsm_x4(bh[0], bbs + kb);
            ldsm_x4(bh[1], bbs + 16 * SROWB + kb);
            #pragma unroll
            for (int mf = 0; mf < 2; ++mf)
                #pragma unroll
                for (int nf = 0; nf < 4; ++nf)
                    MMA16816(acc[mf][nf], ah[mf],
                             bh[nf >> 1][nf & 1], bh[nf >> 1][(nf & 1) + 2]);
        }
    }
    __syncthreads();                 // ldsm done; alias smem as swizzled D-tile

    // ---- fp32 squared-distance tile into swizzled SMEM ----
    float* Dt = (float*)smem;
    #pragma unroll
    for (int mf = 0; mf < 2; ++mf) {
        const int r0l = mw * 32 + mf * 16 + (lane >> 2);
        const float na0 = g_norms[b * HW + row0 + r0l];
        const float na1 = g_norms[b * HW + row0 + r0l + 8];
        const float* nbp = g_norms + b * HW + col0 + nw * 32 + (lane & 3) * 2;
        #pragma unroll
        for (int nf = 0; nf < 4; ++nf) {
            float2 nb = *(const float2*)(nbp + nf * 8);
            int cl = nw * 32 + nf * 8 + (lane & 3) * 2;
            float2 d0 = { na0 + nb.x - 2.f * acc[mf][nf][0],
                          na0 + nb.y - 2.f * acc[mf][nf][1] };
            float2 d1 = { na1 + nb.x - 2.f * acc[mf][nf][2],
                          na1 + nb.y - 2.f * acc[mf][nf][3] };
            *(float2*)&Dt[dsw(r0l, cl)]     = d0;
            *(float2*)&Dt[dsw(r0l + 8, cl)] = d1;
        }
    }
    __syncthreads();

    // ---- packed-key top-4 extraction: 2 tasks/iter, 1 redux per pop ----
    const int ntask = diag ? 128 : 256;
    for (int t0 = w; t0 < ntask; t0 += 32) {
        uint32_t k[2][4];
        #pragma unroll
        for (int u = 0; u < 2; ++u) {
            const int t = t0 + 16 * u;
            if (t < 128) {                              // row task: local cols
                const int rr = t;
                const float4 dv =
                    *(const float4*)&Dt[rr * DPW + ((lane ^ (rr & 31)) << 2)];
                k[u][0] = (__float_as_uint(dv.x) & 0xFFFFFF80u) | (lane * 4 + 0);
                k[u][1] = (__float_as_uint(dv.y) & 0xFFFFFF80u) | (lane * 4 + 1);
                k[u][2] = (__float_as_uint(dv.z) & 0xFFFFFF80u) | (lane * 4 + 2);
                k[u][3] = (__float_as_uint(dv.w) & 0xFFFFFF80u) | (lane * 4 + 3);
                if (diag && (rr >> 2) == lane) k[u][rr & 3] = 0xFFFFFFFFu;
            } else {                                    // col task: local rows
                const int cc = t - 128;
                const int cb = cc >> 2, cq = cc & 3;
                #pragma unroll
                for (int q = 0; q < 4; ++q) {
                    const int r = lane + 32 * q;
                    k[u][q] = (__float_as_uint(
                        Dt[r * DPW + (((cb ^ (r & 31)) << 2) | cq)]) & 0xFFFFFF80u)
                        | (uint32_t)r;
                }
            }
            sort4u(k[u]);
        }

        uint32_t myk[2];
        #pragma unroll
        for (int pp = 0; pp < 4; ++pp) {
            uint32_t g0 = redux_min_u32(k[0][0]);
            uint32_t g1 = redux_min_u32(k[1][0]);
            if (lane == pp) { myk[0] = g0; myk[1] = g1; }
            if (k[0][0] == g0) {
                k[0][0] = k[0][1]; k[0][1] = k[0][2];
                k[0][2] = k[0][3]; k[0][3] = 0xFFFFFFFFu;
            }
            if (k[1][0] == g1) {
                k[1][0] = k[1][1]; k[1][1] = k[1][2];
                k[1][2] = k[1][3]; k[1][3] = 0xFFFFFFFFu;
            }
        }
        if (lane < 4) {
            #pragma unroll
            for (int u = 0; u < 2; ++u) {
                const int t = t0 + 16 * u;
                const int grow = (t < 128) ? (row0 + t) : (col0 + (t - 128));
                const int slot = (t < 128) ? j : i;
                g_pc[(((size_t)(b * HW + grow)) * NSTRIP + slot) * 4 + lane] = myk[u];
            }
        }
    }
}

// ---------------------------------------------------------------------------
// Kernel 3: warp-per-row merge (packed-key pop-min over 32 slot lists) +
// exact fp32 refinement of 8 candidates + margin flagging.
// ---------------------------------------------------------------------------
__global__ void merge_refine_kernel(const float* __restrict__ x,
                                    float* __restrict__ out, int out_size) {
    int gw   = (blockIdx.x * blockDim.x + threadIdx.x) >> 5;
    int lane = threadIdx.x & 31;
    if (gw >= BATCH * HW) return;
    const int b = gw >> 12, rl = gw & 4095;

    const uint4 kk = *(const uint4*)(g_pc + ((size_t)gw * NSTRIP + lane) * 4);

    // B1 = min over tiles of the stored 4th-smallest value (lower bound)
    const uint32_t b1 = redux_min_u32(kk.w);

    // repack: 20-bit value | 12-bit global index (slot*128 + idx7); re-sort
    const uint32_t base = (uint32_t)lane * 128u;
    uint32_t mk[4];
    mk[0] = (kk.x & 0xFFFFF000u) | (base + (kk.x & 0x7Fu));
    mk[1] = (kk.y & 0xFFFFF000u) | (base + (kk.y & 0x7Fu));
    mk[2] = (kk.z & 0xFFFFF000u) | (base + (kk.z & 0x7Fu));
    mk[3] = (kk.w & 0xFFFFF000u) | (base + (kk.w & 0x7Fu));
    sort4u(mk);

    uint32_t gks[8];
    #pragma unroll
    for (int pp = 0; pp < 8; ++pp) {
        uint32_t gv = redux_min_u32(mk[0]);
        gks[pp] = gv;
        if (mk[0] == gv) {
            mk[0] = mk[1]; mk[1] = mk[2]; mk[2] = mk[3]; mk[3] = 0xFFFFFFFFu;
        }
    }

    // exact fp32 refinement of the 8 global candidates
    const float* xb = x + (size_t)b * HW * CDIM;
    const float* xr = xb + (size_t)rl * CDIM + lane * 8;
    float4 a0 = *(const float4*)xr;
    float4 a1 = *(const float4*)(xr + 4);
    const float nr = g_norms[b * HW + rl];

    float m1 = FLT_MAX, m2 = FLT_MAX; int j1 = 0, j2 = 0;
    #pragma unroll
    for (int k = 0; k < 8; ++k) {
        const int c = (int)(gks[k] & 0xFFFu);
        const float* xc = xb + (size_t)c * CDIM + lane * 8;
        float4 c0 = *(const float4*)xc;
        float4 c1 = *(const float4*)(xc + 4);
        float s = a0.x*c0.x + a0.y*c0.y + a0.z*c0.z + a0.w*c0.w
                + a1.x*c1.x + a1.y*c1.y + a1.z*c1.z + a1.w*c1.w;
        #pragma unroll
        for (int off = 16; off; off >>= 1) s += __shfl_xor_sync(0xffffffffu, s, off);
        float D = nr + g_norms[b * HW + c] - 2.f * s;
        if (ltp(D, c, m1, j1)) { m2 = m1; j2 = j1; m1 = D; j1 = c; }
        else if (ltp(D, c, m2, j2)) { m2 = D; j2 = c; }
    }

    if (lane == 0) {
        out[(size_t)b * HW + rl] = predict(m1, m2);
        if (out_size >= 2 * BATCH * HW)
            out[(size_t)BATCH * HW + (size_t)b * HW + rl] = (float)j1;
        // bound: stored values are lower bounds of bf16 D; exact >= bound-MARGIN
        float bound = fminf(__uint_as_float(b1 & 0xFFFFFF80u),
                            __uint_as_float(gks[7] & 0xFFFFF000u));
        if (m2 > bound - MARGIN) {
            int fi = atomicAdd(&g_flagcnt, 1);
            g_flaglist[fi] = gw;
        }
    }
}

// ---------------------------------------------------------------------------
// Kernel 4: exact full-row rescan for flagged rows (expected ~0 rows).
// ---------------------------------------------------------------------------
__global__ void fallback_kernel(const float* __restrict__ x,
                                float* __restrict__ out, int out_size) {
    __shared__ float sv1[256], sv2[256];
    __shared__ int   si1[256];
    const int n = g_flagcnt;
    for (int fi = blockIdx.x; fi < n; fi += gridDim.x) {
        const int rowg = g_flaglist[fi];
        const int b = rowg >> 12, r = rowg & 4095;
        const float* xb = x + (size_t)b * HW * CDIM;
        const float* xr = xb + (size_t)r * CDIM;
        const float  nr = g_norms[rowg];
        float v1 = FLT_MAX, v2 = FLT_MAX; int i1 = 0x7fffffff;
        for (int c = threadIdx.x; c < HW; c += 256) {
            if (c == r) continue;
            const float4* xc = (const float4*)(xb + (size_t)c * CDIM);
            float s = 0.f;
            #pragma unroll
            for (int d = 0; d < 64; ++d) {
                float4 va = ((const float4*)xr)[d];
                float4 vb = xc[d];
                s += va.x*vb.x + va.y*vb.y + va.z*vb.z + va.w*vb.w;
            }
            float D = nr + g_norms[b * HW + c] - 2.f * s;
            if (ltp(D, c, v1, i1)) { v2 = v1; v1 = D; i1 = c; }
            else if (D < v2) { v2 = D; }
        }
        sv1[threadIdx.x] = v1; sv2[threadIdx.x] = v2; si1[threadIdx.x] = i1;
        __syncthreads();
        for (int off = 128; off; off >>= 1) {
            if (threadIdx.x < off) {
                float b1 = sv1[threadIdx.x + off], b2 = sv2[threadIdx.x + off];
                int   bi = si1[threadIdx.x + off];
                float a1v = sv1[threadIdx.x]; int a1i = si1[threadIdx.x];
                if (ltp(b1, bi, a1v, a1i)) {
                    sv2[threadIdx.x] = fminf(a1v, b2);
                    sv1[threadIdx.x] = b1; si1[threadIdx.x] = bi;
                } else {
                    sv2[threadIdx.x] = fminf(sv2[threadIdx.x], b1);
                }
            }
            __syncthreads();
        }
        if (threadIdx.x == 0) {
            out[(size_t)b * HW + r] = predict(sv1[0], sv2[0]);
            if (out_size >= 2 * BATCH * HW)
                out[(size_t)BATCH * HW + (size_t)b * HW + r] = (float)si1[0];
        }
        __syncthreads();
    }
}

// ---------------------------------------------------------------------------
extern "C" void kernel_launch(void* const* d_in, const int* in_sizes, int n_in,
                              void* d_out, int out_size) {
    const float* x   = (const float*)d_in[0];
    float*       out = (float*)d_out;

    convert_norms_kernel<<<BATCH * HW / 8, 256>>>(x);

    cudaFuncSetAttribute(fcm_pair_kernel,
                         cudaFuncAttributeMaxDynamicSharedMemorySize, TOTSMEM);
    dim3 grid(NPAIR, BATCH);
    fcm_pair_kernel<<<grid, 512, TOTSMEM>>>();

    merge_refine_kernel<<<BATCH * HW / 8, 256>>>(x, out, out_size);
    fallback_kernel<<<256, 256>>>(x, out, out_size);
}

// round 10
// speedup vs baseline: 6.8094x; 1.1434x over previous
#include <cuda_runtime.h>
#include <cuda_bf16.h>
#include <cstdint>
#include <float.h>
#include <math.h>

#define BATCH 4
#define HW    4096
#define CDIM  256
#define NSTRIP 32
#define NPAIR  528
#define EPSQ  1e-9f
#define TLC   0.6f
#define LC    2.0f
#define MARGIN 0.75f
#define SROWB 144                 // bf16 staging row stride (128B data + 16B pad)
#define TENB  (128 * SROWB)
#define STAGEB (2 * TENB)
#define TOTSMEM (2 * STAGEB)      // 73728 B per CTA (Dt 64KB aliases this)
#define DPW   128                 // D-tile words per row (XOR-swizzled blocks)

// static device scratch
__device__ __nv_bfloat16 g_xhi[BATCH * HW * CDIM];
__device__ float    g_norms[BATCH * HW];
__device__ uint32_t g_pc[(size_t)BATCH * HW * NSTRIP * 4];  // packed (val25|idx7)
__device__ int      g_flagcnt;
__device__ int      g_flaglist[BATCH * HW];

// ---------------------------------------------------------------------------
__device__ __forceinline__ uint32_t smem_u32(const void* p) {
    uint32_t a;
    asm("{ .reg .u64 t; cvta.to.shared.u64 t, %1; cvt.u32.u64 %0, t; }"
        : "=r"(a) : "l"(p));
    return a;
}
__device__ __forceinline__ void cp16(uint32_t dst, const void* src) {
    asm volatile("cp.async.cg.shared.global [%0], [%1], 16;" :: "r"(dst), "l"(src));
}
__device__ __forceinline__ void cp_commit() {
    asm volatile("cp.async.commit_group;" ::: "memory");
}
template <int N> __device__ __forceinline__ void cp_wait() {
    asm volatile("cp.async.wait_group %0;" :: "n"(N) : "memory");
}
__device__ __forceinline__ void ldsm_x4(uint32_t (&r)[4], uint32_t addr) {
    asm volatile("ldmatrix.sync.aligned.m8n8.x4.shared.b16 {%0,%1,%2,%3}, [%4];"
                 : "=r"(r[0]), "=r"(r[1]), "=r"(r[2]), "=r"(r[3]) : "r"(addr));
}
__device__ __forceinline__ uint32_t redux_min_u32(uint32_t v) {
    uint32_t r;
    asm volatile("redux.sync.min.u32 %0, %1, 0xffffffff;" : "=r"(r) : "r"(v));
    return r;
}
#define MMA16816(d, a, b0_, b1_)                                                 \
    asm volatile("mma.sync.aligned.m16n8k16.row.col.f32.bf16.bf16.f32 "          \
                 "{%0,%1,%2,%3}, {%4,%5,%6,%7}, {%8,%9}, {%0,%1,%2,%3};"         \
                 : "+f"((d)[0]), "+f"((d)[1]), "+f"((d)[2]), "+f"((d)[3])        \
                 : "r"((a)[0]), "r"((a)[1]), "r"((a)[2]), "r"((a)[3]),           \
                   "r"(b0_), "r"(b1_))

// swizzled D-tile word index for logical (row r, col c)
__device__ __forceinline__ int dsw(int r, int c) {
    return r * DPW + ((((c >> 2) ^ (r & 31)) << 2) | (c & 3));
}
__device__ __forceinline__ bool ltp(float av, int ai, float bv, int bi) {
    return (av < bv) || (av == bv && ai < bi);
}
// ascending compare-exchange on packed keys (2 instr: min + max)
__device__ __forceinline__ void ceu(uint32_t& a, uint32_t& b) {
    uint32_t mn = min(a, b);
    b = max(a, b);
    a = mn;
}
__device__ __forceinline__ void sort4u(uint32_t (&k)[4]) {
    ceu(k[0], k[1]); ceu(k[2], k[3]);
    ceu(k[0], k[2]); ceu(k[1], k[3]);
    ceu(k[1], k[2]);
}
__device__ __forceinline__ float predict(float m1, float m2) {
    float d1 = sqrtf(fmaxf(m1, 0.f) + EPSQ);
    float d2 = sqrtf(fmaxf(m2, 0.f) + EPSQ);
    float e  = expf(d1);
    return (d1 / d2 < TLC) ? 2.f / (1.f + e) : 2.f / (1.f + LC * e);
}

// ---------------------------------------------------------------------------
// Kernel 1: fused bf16 convert + fp32 row norms (one warp per row)
// ---------------------------------------------------------------------------
__global__ void convert_norms_kernel(const float* __restrict__ x) {
    if (blockIdx.x == 0 && threadIdx.x == 0) g_flagcnt = 0;
    int gw   = (blockIdx.x * blockDim.x + threadIdx.x) >> 5;
    int lane = threadIdx.x & 31;
    if (gw >= BATCH * HW) return;
    const float* xr = x + (size_t)gw * CDIM + lane * 8;
    float4 v0 = *(const float4*)xr;
    float4 v1 = *(const float4*)(xr + 4);
    float s = v0.x*v0.x + v0.y*v0.y + v0.z*v0.z + v0.w*v0.w
            + v1.x*v1.x + v1.y*v1.y + v1.z*v1.z + v1.w*v1.w;
    __nv_bfloat162 p0(__float2bfloat16(v0.x), __float2bfloat16(v0.y));
    __nv_bfloat162 p1(__float2bfloat16(v0.z), __float2bfloat16(v0.w));
    __nv_bfloat162 p2(__float2bfloat16(v1.x), __float2bfloat16(v1.y));
    __nv_bfloat162 p3(__float2bfloat16(v1.z), __float2bfloat16(v1.w));
    uint4 u;
    u.x = *(uint32_t*)&p0; u.y = *(uint32_t*)&p1;
    u.z = *(uint32_t*)&p2; u.w = *(uint32_t*)&p3;
    ((uint4*)g_xhi)[(size_t)gw * 32 + lane] = u;
    #pragma unroll
    for (int o = 16; o; o >>= 1) s += __shfl_xor_sync(0xffffffffu, s, o);
    if (lane == 0) g_norms[gw] = s;
}

// ---------------------------------------------------------------------------
// Kernel 2: single-pass bf16 Gram tile-pair + packed-key top-4 per row/col.
// Occupancy 2: extraction/latency phase of one CTA overlaps MMA of the other.
// ---------------------------------------------------------------------------
__global__ __launch_bounds__(512, 2)
void fcm_pair_kernel() {
    extern __shared__ __align__(16) char smem[];
    const uint32_t sbase = smem_u32(smem);

    const int tid  = threadIdx.x;
    const int lane = tid & 31;
    const int w    = tid >> 5;
    const int mw   = w >> 2;
    const int nw   = w & 3;
    const int b    = blockIdx.y;

    int p = blockIdx.x;
    int i = (int)((65.0f - sqrtf(4225.0f - 8.0f * (float)p)) * 0.5f);
    while ((i + 1) * (65 - (i + 1)) / 2 <= p) ++i;
    while (i * (65 - i) / 2 > p) --i;
    const int j = i + (p - i * (65 - i) / 2);
    const int row0 = i * 128, col0 = j * 128;
    const bool diag = (i == j);

    const __nv_bfloat16* xb = g_xhi + (size_t)b * HW * CDIM;
    const int lrow = ((lane >> 3) & 1) * 8 + (lane & 7);
    const int lkb  = (lane >> 4) * 16;

    auto stage = [&](int kc) {
        const uint32_t dst = sbase + (uint32_t)((kc & 1) * STAGEB);
        #pragma unroll
        for (int o = 0; o < 2; ++o) {
            int lin = tid + o * 512;
            int r = lin >> 3, gg = lin & 7;
            cp16(dst + (uint32_t)(r * SROWB + gg * 16),
                 xb + (size_t)(row0 + r) * CDIM + kc * 64 + gg * 8);
            cp16(dst + TENB + (uint32_t)(r * SROWB + gg * 16),
                 xb + (size_t)(col0 + r) * CDIM + kc * 64 + gg * 8);
        }
        cp_commit();
    };
    stage(0);

    float acc[2][4][4];
    #pragma unroll
    for (int mf = 0; mf < 2; ++mf)
        #pragma unroll
        for (int nf = 0; nf < 4; ++nf)
            #pragma unroll
            for (int e = 0; e < 4; ++e) acc[mf][nf][e] = 0.f;

    for (int kc = 0; kc < 4; ++kc) {
        cp_wait<0>();
        __syncthreads();
        if (kc < 3) stage(kc + 1);
        const uint32_t bb  = sbase + (uint32_t)((kc & 1) * STAGEB);
        const uint32_t ab  = bb + (uint32_t)((mw * 32 + lrow) * SROWB);
        const uint32_t bbs = bb + TENB + (uint32_t)((nw * 32 + lrow) * SROWB);
        #pragma unroll
        for (int ks = 0; ks < 4; ++ks) {
            const uint32_t kb = (uint32_t)(ks * 32 + lkb);
            uint32_t ah[2][4], bh[2][4];
            ldsm_x4(ah[0], ab + kb);
            ldsm_x4(ah[1], ab + 16 * SROWB + kb);
            ldsm_x4(bh[0], bbs + kb);
            ldsm_x4(bh[1], bbs + 16 * SROWB + kb);
            #pragma unroll
            for (int mf = 0; mf < 2; ++mf)
                #pragma unroll
                for (int nf = 0; nf < 4; ++nf)
                    MMA16816(acc[mf][nf], ah[mf],
                             bh[nf >> 1][nf & 1], bh[nf >> 1][(nf & 1) + 2]);
        }
    }
    __syncthreads();                 // ldsm done; alias smem as swizzled D-tile

    // ---- fp32 squared-distance tile into swizzled SMEM ----
    float* Dt = (float*)smem;
    #pragma unroll
    for (int mf = 0; mf < 2; ++mf) {
        const int r0l = mw * 32 + mf * 16 + (lane >> 2);
        const float na0 = g_norms[b * HW + row0 + r0l];
        const float na1 = g_norms[b * HW + row0 + r0l + 8];
        const float* nbp = g_norms + b * HW + col0 + nw * 32 + (lane & 3) * 2;
        #pragma unroll
        for (int nf = 0; nf < 4; ++nf) {
            float2 nb = *(const float2*)(nbp + nf * 8);
            int cl = nw * 32 + nf * 8 + (lane & 3) * 2;
            float2 d0 = { na0 + nb.x - 2.f * acc[mf][nf][0],
                          na0 + nb.y - 2.f * acc[mf][nf][1] };
            float2 d1 = { na1 + nb.x - 2.f * acc[mf][nf][2],
                          na1 + nb.y - 2.f * acc[mf][nf][3] };
            *(float2*)&Dt[dsw(r0l, cl)]     = d0;
            *(float2*)&Dt[dsw(r0l + 8, cl)] = d1;
        }
    }
    __syncthreads();

    // ---- packed-key top-4 extraction: 2 tasks/iter, 1 redux per pop ----
    const int ntask = diag ? 128 : 256;
    for (int t0 = w; t0 < ntask; t0 += 32) {
        uint32_t k[2][4];
        #pragma unroll
        for (int u = 0; u < 2; ++u) {
            const int t = t0 + 16 * u;
            if (t < 128) {                              // row task: local cols
                const int rr = t;
                const float4 dv =
                    *(const float4*)&Dt[rr * DPW + ((lane ^ (rr & 31)) << 2)];
                k[u][0] = (__float_as_uint(dv.x) & 0xFFFFFF80u) | (lane * 4 + 0);
                k[u][1] = (__float_as_uint(dv.y) & 0xFFFFFF80u) | (lane * 4 + 1);
                k[u][2] = (__float_as_uint(dv.z) & 0xFFFFFF80u) | (lane * 4 + 2);
                k[u][3] = (__float_as_uint(dv.w) & 0xFFFFFF80u) | (lane * 4 + 3);
                if (diag && (rr >> 2) == lane) k[u][rr & 3] = 0xFFFFFFFFu;
            } else {                                    // col task: local rows
                const int cc = t - 128;
                const int cb = cc >> 2, cq = cc & 3;
                #pragma unroll
                for (int q = 0; q < 4; ++q) {
                    const int r = lane + 32 * q;
                    k[u][q] = (__float_as_uint(
                        Dt[r * DPW + (((cb ^ (r & 31)) << 2) | cq)]) & 0xFFFFFF80u)
                        | (uint32_t)r;
                }
            }
            sort4u(k[u]);
        }

        uint32_t myk[2];
        #pragma unroll
        for (int pp = 0; pp < 4; ++pp) {
            uint32_t g0 = redux_min_u32(k[0][0]);
            uint32_t g1 = redux_min_u32(k[1][0]);
            if (lane == pp) { myk[0] = g0; myk[1] = g1; }
            if (k[0][0] == g0) {
                k[0][0] = k[0][1]; k[0][1] = k[0][2];
                k[0][2] = k[0][3]; k[0][3] = 0xFFFFFFFFu;
            }
            if (k[1][0] == g1) {
                k[1][0] = k[1][1]; k[1][1] = k[1][2];
                k[1][2] = k[1][3]; k[1][3] = 0xFFFFFFFFu;
            }
        }
        if (lane < 4) {
            #pragma unroll
            for (int u = 0; u < 2; ++u) {
                const int t = t0 + 16 * u;
                const int grow = (t < 128) ? (row0 + t) : (col0 + (t - 128));
                const int slot = (t < 128) ? j : i;
                g_pc[(((size_t)(b * HW + grow)) * NSTRIP + slot) * 4 + lane] = myk[u];
            }
        }
    }
}

// ---------------------------------------------------------------------------
// Kernel 3: warp-per-row merge (packed-key pop-min over 32 slot lists) +
// exact fp32 refinement of 8 candidates + margin flagging.
// ---------------------------------------------------------------------------
__global__ void merge_refine_kernel(const float* __restrict__ x,
                                    float* __restrict__ out, int out_size) {
    int gw   = (blockIdx.x * blockDim.x + threadIdx.x) >> 5;
    int lane = threadIdx.x & 31;
    if (gw >= BATCH * HW) return;
    const int b = gw >> 12, rl = gw & 4095;

    const uint4 kk = *(const uint4*)(g_pc + ((size_t)gw * NSTRIP + lane) * 4);

    // B1 = min over tiles of the stored 4th-smallest value (lower bound)
    const uint32_t b1 = redux_min_u32(kk.w);

    // repack: 20-bit value | 12-bit global index (slot*128 + idx7); re-sort
    const uint32_t base = (uint32_t)lane * 128u;
    uint32_t mk[4];
    mk[0] = (kk.x & 0xFFFFF000u) | (base + (kk.x & 0x7Fu));
    mk[1] = (kk.y & 0xFFFFF000u) | (base + (kk.y & 0x7Fu));
    mk[2] = (kk.z & 0xFFFFF000u) | (base + (kk.z & 0x7Fu));
    mk[3] = (kk.w & 0xFFFFF000u) | (base + (kk.w & 0x7Fu));
    sort4u(mk);

    uint32_t gks[8];
    #pragma unroll
    for (int pp = 0; pp < 8; ++pp) {
        uint32_t gv = redux_min_u32(mk[0]);
        gks[pp] = gv;
        if (mk[0] == gv) {
            mk[0] = mk[1]; mk[1] = mk[2]; mk[2] = mk[3]; mk[3] = 0xFFFFFFFFu;
        }
    }

    // exact fp32 refinement of the 8 global candidates
    const float* xb = x + (size_t)b * HW * CDIM;
    const float* xr = xb + (size_t)rl * CDIM + lane * 8;
    float4 a0 = *(const float4*)xr;
    float4 a1 = *(const float4*)(xr + 4);
    const float nr = g_norms[b * HW + rl];

    float m1 = FLT_MAX, m2 = FLT_MAX; int j1 = 0, j2 = 0;
    #pragma unroll
    for (int k = 0; k < 8; ++k) {
        const int c = (int)(gks[k] & 0xFFFu);
        const float* xc = xb + (size_t)c * CDIM + lane * 8;
        float4 c0 = *(const float4*)xc;
        float4 c1 = *(const float4*)(xc + 4);
        float s = a0.x*c0.x + a0.y*c0.y + a0.z*c0.z + a0.w*c0.w
                + a1.x*c1.x + a1.y*c1.y + a1.z*c1.z + a1.w*c1.w;
        #pragma unroll
        for (int off = 16; off; off >>= 1) s += __shfl_xor_sync(0xffffffffu, s, off);
        float D = nr + g_norms[b * HW + c] - 2.f * s;
        if (ltp(D, c, m1, j1)) { m2 = m1; j2 = j1; m1 = D; j1 = c; }
        else if (ltp(D, c, m2, j2)) { m2 = D; j2 = c; }
    }

    if (lane == 0) {
        out[(size_t)b * HW + rl] = predict(m1, m2);
        if (out_size >= 2 * BATCH * HW)
            out[(size_t)BATCH * HW + (size_t)b * HW + rl] = (float)j1;
        // bound: stored values are lower bounds of bf16 D; exact >= bound-MARGIN
        float bound = fminf(__uint_as_float(b1 & 0xFFFFFF80u),
                            __uint_as_float(gks[7] & 0xFFFFF000u));
        if (m2 > bound - MARGIN) {
            int fi = atomicAdd(&g_flagcnt, 1);
            g_flaglist[fi] = gw;
        }
    }
}

// ---------------------------------------------------------------------------
// Kernel 4: exact full-row rescan for flagged rows (expected ~0 rows).
// ---------------------------------------------------------------------------
__global__ void fallback_kernel(const float* __restrict__ x,
                                float* __restrict__ out, int out_size) {
    __shared__ float sv1[256], sv2[256];
    __shared__ int   si1[256];
    const int n = g_flagcnt;
    for (int fi = blockIdx.x; fi < n; fi += gridDim.x) {
        const int rowg = g_flaglist[fi];
        const int b = rowg >> 12, r = rowg & 4095;
        const float* xb = x + (size_t)b * HW * CDIM;
        const float* xr = xb + (size_t)r * CDIM;
        const float  nr = g_norms[rowg];
        float v1 = FLT_MAX, v2 = FLT_MAX; int i1 = 0x7fffffff;
        for (int c = threadIdx.x; c < HW; c += 256) {
            if (c == r) continue;
            const float4* xc = (const float4*)(xb + (size_t)c * CDIM);
            float s = 0.f;
            #pragma unroll
            for (int d = 0; d < 64; ++d) {
                float4 va = ((const float4*)xr)[d];
                float4 vb = xc[d];
                s += va.x*vb.x + va.y*vb.y + va.z*vb.z + va.w*vb.w;
            }
            float D = nr + g_norms[b * HW + c] - 2.f * s;
            if (ltp(D, c, v1, i1)) { v2 = v1; v1 = D; i1 = c; }
            else if (D < v2) { v2 = D; }
        }
        sv1[threadIdx.x] = v1; sv2[threadIdx.x] = v2; si1[threadIdx.x] = i1;
        __syncthreads();
        for (int off = 128; off; off >>= 1) {
            if (threadIdx.x < off) {
                float b1 = sv1[threadIdx.x + off], b2 = sv2[threadIdx.x + off];
                int   bi = si1[threadIdx.x + off];
                float a1v = sv1[threadIdx.x]; int a1i = si1[threadIdx.x];
                if (ltp(b1, bi, a1v, a1i)) {
                    sv2[threadIdx.x] = fminf(a1v, b2);
                    sv1[threadIdx.x] = b1; si1[threadIdx.x] = bi;
                } else {
                    sv2[threadIdx.x] = fminf(sv2[threadIdx.x], b1);
                }
            }
            __syncthreads();
        }
        if (threadIdx.x == 0) {
            out[(size_t)b * HW + r] = predict(sv1[0], sv2[0]);
            if (out_size >= 2 * BATCH * HW)
                out[(size_t)BATCH * HW + (size_t)b * HW + r] = (float)si1[0];
        }
        __syncthreads();
    }
}

// ---------------------------------------------------------------------------
extern "C" void kernel_launch(void* const* d_in, const int* in_sizes, int n_in,
                              void* d_out, int out_size) {
    const float* x   = (const float*)d_in[0];
    float*       out = (float*)d_out;

    convert_norms_kernel<<<BATCH * HW / 8, 256>>>(x);

    cudaFuncSetAttribute(fcm_pair_kernel,
                         cudaFuncAttributeMaxDynamicSharedMemorySize, TOTSMEM);
    dim3 grid(NPAIR, BATCH);
    fcm_pair_kernel<<<grid, 512, TOTSMEM>>>();

    merge_refine_kernel<<<BATCH * HW / 8, 256>>>(x, out, out_size);
    fallback_kernel<<<256, 256>>>(x, out, out_size);
}